// round 10
// baseline (speedup 1.0000x reference)
#include <cuda_runtime.h>
#include <math.h>

// x: (4,256,128,128)  xyz: (4,3,128,128)
// folded blocks: NB=128 (b*32 + e*4 + f1*2 + f2), c=32, tile 64x64, M=16 centers
#define NB 128
#define MCNT 16

// ---------------- scratch (static __device__, no allocation) ----------------
__device__ float  d_cen [NB*512];         // pooled centers (unnormalized)
__device__ float  d_ncen[NB*512];         // l2-normalized centers
__device__ float  d_ngeo[16*16*4];        // normalized xyz centers, padded to 4
__device__ float  d_sgeo2[16*16*4096];    // sigmoid(geo)^2 table  [g][m][n]  (4 MB)
__device__ float  d_sim [NB*16*4096];     // 33.5 MB sim cache (tf32-rounded values)
__device__ float  d_Tp  [1024*512];       // partial T = sim@x  (per bb-chunk)
__device__ float  d_Sp  [1024*16];        // partial rowsum(sim)
__device__ float  d_Gp  [1024*256];       // partial Gram(sim)
__device__ float  d_dout[NB*512];         // dense_out (16m x 32c per bb)
__device__ double d_gstats[8];            // per-batch sum, sumsq
__device__ float  d_weff[4*256*256];      // GN-folded projection weights
__device__ float  d_beff[4*256];          // GN-folded projection bias
__device__ float  d_WD  [16*256*128];     // fused weights (tf32-rounded)

__device__ __forceinline__ float sigmoidf(float z) { return 1.f / (1.f + __expf(-z)); }
__device__ __forceinline__ float f2tf(float f) {
    unsigned u; asm("cvt.rna.tf32.f32 %0, %1;" : "=r"(u) : "f"(f));
    return __uint_as_float(u);
}

// ---------------- kernel A: pooled centers, warp per (bb,m,c), float4 ----------------
__global__ void k_centers(const float* __restrict__ x) {
    int w = blockIdx.x * 8 + (threadIdx.x >> 5);   // 65536 warps
    int lane = threadIdx.x & 31;
    int bb = w >> 9; int rem = w & 511; int m = rem >> 5; int c = rem & 31;
    int b = bb >> 5, e = (bb >> 2) & 7, f1 = (bb >> 1) & 1, f2 = bb & 1;
    int pi = m >> 2, pj = m & 3;
    const float* xp = x + (((size_t)(b * 256 + e * 32 + c)) << 14)
                        + (f1 * 64 + pi * 16) * 128 + f2 * 64 + pj * 16;
    float acc = 0.f;
    #pragma unroll
    for (int r = 0; r < 2; r++) {
        int idx = r * 32 + lane;              // 0..63 float4s
        int ii = idx >> 2, jj4 = idx & 3;
        float4 v = *(const float4*)(xp + ii * 128 + jj4 * 4);
        acc += (v.x + v.y) + (v.z + v.w);
    }
    #pragma unroll
    for (int o = 16; o; o >>= 1) acc += __shfl_down_sync(0xffffffffu, acc, o);
    if (lane == 0) d_cen[w] = acc * (1.f / 256.f);
}

// ---------------- kernel A2: normalize centers, warp per (bb,m) ----------------
__global__ void k_ncen() {
    int q = blockIdx.x * 8 + (threadIdx.x >> 5);   // 2048 warps
    int c = threadIdx.x & 31;
    float v = d_cen[q * 32 + c];
    float ss = v * v;
    #pragma unroll
    for (int o = 16; o; o >>= 1) ss += __shfl_xor_sync(0xffffffffu, ss, o);
    float inv = 1.f / fmaxf(sqrtf(ss), 1e-12f);
    d_ncen[q * 32 + c] = v * inv;
}

// ---------------- kernel A3: normalized xyz centers + zero stats ----------------
__global__ void k_geo(const float* __restrict__ xyz) {
    int t = threadIdx.x;
    if (t < 8) d_gstats[t] = 0.0;
    int g = t >> 4, m = t & 15;
    int b = g >> 2, f1 = (g >> 1) & 1, f2 = g & 1;
    int pi = m >> 2, pj = m & 3;
    const float* base = xyz + (((size_t)(b * 3)) << 14)
                            + (f1 * 64 + pi * 16) * 128 + f2 * 64 + pj * 16;
    float s0 = 0.f, s1 = 0.f, s2 = 0.f;
    for (int ii = 0; ii < 16; ii++)
        for (int jj = 0; jj < 16; jj++) {
            int off = ii * 128 + jj;
            s0 += base[off];
            s1 += base[off + 16384];
            s2 += base[off + 32768];
        }
    s0 *= (1.f / 256.f); s1 *= (1.f / 256.f); s2 *= (1.f / 256.f);
    float inv = 1.f / fmaxf(sqrtf(s0 * s0 + s1 * s1 + s2 * s2), 1e-12f);
    int o = (g * 16 + m) * 4;
    d_ngeo[o] = s0 * inv; d_ngeo[o + 1] = s1 * inv; d_ngeo[o + 2] = s2 * inv; d_ngeo[o + 3] = 0.f;
}

// ---------------- kernel A4: sim_geo^2 table [g][m][n], grid (16 g, 64 i) ----------------
__global__ void k_geo2(const float* __restrict__ xyz,
                       const float* __restrict__ salpha, const float* __restrict__ sbeta) {
    int g = blockIdx.x, i = blockIdx.y;
    int t = threadIdx.x;
    int j = t & 63, mg = t >> 6;                 // 4 m-groups of 4
    int bg = g >> 2, f1 = (g >> 1) & 1, f2 = g & 1;
    float alpha = salpha[0], beta = sbeta[0];
    const float* base = xyz + (((size_t)(bg * 3)) << 14) + (f1 * 64 + i) * 128 + f2 * 64 + j;
    float p0 = base[0], p1 = base[16384], p2 = base[32768];
    float inv = 1.f / fmaxf(sqrtf(p0 * p0 + p1 * p1 + p2 * p2), 1e-12f);
    p0 *= inv; p1 *= inv; p2 *= inv;
    #pragma unroll
    for (int mm = 0; mm < 4; mm++) {
        int m = mg * 4 + mm;
        const float* ng = d_ngeo + (g * 16 + m) * 4;
        float gd = ng[0] * p0 + ng[1] * p1 + ng[2] * p2;
        float sg = sigmoidf(beta + alpha * gd);
        d_sgeo2[(g * 16 + m) * 4096 + i * 64 + j] = sg * sg;
    }
}

// ------- fused kernel: sim (phase A) + T/S/G reduction (phase B), big smem -------
// CTA per (bb, 8-row chunk). smem: x tile 32x512 (stride 516), sim 16x512, ncen.
#define XS 516
#define SMEMT ((32*XS + 16*XS + 512) * 4)
__global__ __launch_bounds__(256) void k_simT(const float* __restrict__ x,
                                              const float* __restrict__ salpha,
                                              const float* __restrict__ sbeta) {
    extern __shared__ float SB[];
    float* s_x    = SB;                   // [32][XS]
    float* s_sim  = SB + 32 * XS;         // [16][XS]
    float* s_ncen = SB + 48 * XS;         // [512]

    int blk = blockIdx.x;                  // 0..1023
    int bb = blk >> 3, chunk = blk & 7;
    int t = threadIdx.x;
    int m = t >> 4, jq = t & 15, j0 = jq * 4;
    int b = bb >> 5, e = (bb >> 2) & 7, f1 = (bb >> 1) & 1, f2 = bb & 1;
    int g = bb & 15;        // reference's tile() quirk: geo block = bb % 16
    float alpha = salpha[0], beta = sbeta[0];

    s_ncen[t]       = d_ncen[bb * 512 + t];
    s_ncen[t + 256] = d_ncen[bb * 512 + t + 256];

    const float* xb = x + (((size_t)(b * 256 + e * 32)) << 14) + (f1 * 64) * 128 + f2 * 64;
    float* simb = d_sim + (size_t)bb * 65536 + m * 4096;
    const float* sgb = d_sgeo2 + (g * 16 + m) * 4096;
    __syncthreads();

    // ---- phase A: compute sim rows, keep x + sim resident ----
    for (int ir = 0; ir < 8; ir++) {
        int i = chunk * 8 + ir;
        #pragma unroll
        for (int r = 0; r < 2; r++) {
            int v = r * 256 + t;
            int c = v >> 4, j4 = v & 15;
            *(float4*)&s_x[c * XS + ir * 64 + j4 * 4] =
                *(const float4*)(xb + c * 16384 + i * 128 + j4 * 4);
        }
        __syncthreads();
        float d0 = 0.f, d1 = 0.f, d2 = 0.f, d3 = 0.f;
        float n0 = 0.f, n1 = 0.f, n2 = 0.f, n3 = 0.f;
        #pragma unroll
        for (int c4 = 0; c4 < 8; c4++) {
            float4 nc = *(const float4*)&s_ncen[m * 32 + c4 * 4];
            float4 xa = *(const float4*)&s_x[(c4 * 4 + 0) * XS + ir * 64 + j0];
            float4 xb_ = *(const float4*)&s_x[(c4 * 4 + 1) * XS + ir * 64 + j0];
            float4 xc = *(const float4*)&s_x[(c4 * 4 + 2) * XS + ir * 64 + j0];
            float4 xd = *(const float4*)&s_x[(c4 * 4 + 3) * XS + ir * 64 + j0];
            d0 += nc.x * xa.x + nc.y * xb_.x + nc.z * xc.x + nc.w * xd.x;
            d1 += nc.x * xa.y + nc.y * xb_.y + nc.z * xc.y + nc.w * xd.y;
            d2 += nc.x * xa.z + nc.y * xb_.z + nc.z * xc.z + nc.w * xd.z;
            d3 += nc.x * xa.w + nc.y * xb_.w + nc.z * xc.w + nc.w * xd.w;
            n0 += xa.x * xa.x + xb_.x * xb_.x + xc.x * xc.x + xd.x * xd.x;
            n1 += xa.y * xa.y + xb_.y * xb_.y + xc.y * xc.y + xd.y * xd.y;
            n2 += xa.z * xa.z + xb_.z * xb_.z + xc.z * xc.z + xd.z * xd.z;
            n3 += xa.w * xa.w + xb_.w * xb_.w + xc.w * xc.w + xd.w * xd.w;
        }
        float4 sg2 = *(const float4*)(sgb + i * 64 + j0);
        float i0 = 1.f / fmaxf(sqrtf(n0), 1e-12f);
        float i1 = 1.f / fmaxf(sqrtf(n1), 1e-12f);
        float i2 = 1.f / fmaxf(sqrtf(n2), 1e-12f);
        float i3 = 1.f / fmaxf(sqrtf(n3), 1e-12f);
        float s0 = f2tf(sigmoidf(beta + alpha * d0 * i0) * sg2.x);
        float s1 = f2tf(sigmoidf(beta + alpha * d1 * i1) * sg2.y);
        float s2 = f2tf(sigmoidf(beta + alpha * d2 * i2) * sg2.z);
        float s3 = f2tf(sigmoidf(beta + alpha * d3 * i3) * sg2.w);
        float4 sv = make_float4(s0, s1, s2, s3);
        *(float4*)&s_sim[m * XS + ir * 64 + j0] = sv;
        *(float4*)(simb + i * 64 + j0) = sv;
    }
    __syncthreads();

    // ---- phase B: T = sim@x^T, S = rowsum(sim), G = sim@sim^T from resident tiles ----
    int c = jq;                            // T roles (m, c) and (m, c+16); G roles (m, c)
    float T0 = 0.f, T1 = 0.f, Greg = 0.f, Sacc = 0.f;
    #pragma unroll 4
    for (int k4 = 0; k4 < 128; k4++) {
        float4 a  = *(const float4*)&s_sim[m * XS + k4 * 4];
        float4 bq = *(const float4*)&s_sim[c * XS + k4 * 4];
        float4 xa = *(const float4*)&s_x[c * XS + k4 * 4];
        float4 xc = *(const float4*)&s_x[(c + 16) * XS + k4 * 4];
        T0 += a.x * xa.x + a.y * xa.y + a.z * xa.z + a.w * xa.w;
        T1 += a.x * xc.x + a.y * xc.y + a.z * xc.z + a.w * xc.w;
        Greg += a.x * bq.x + a.y * bq.y + a.z * bq.z + a.w * bq.w;
        if (c == 0) Sacc += (a.x + a.y) + (a.z + a.w);
    }
    d_Tp[blk * 512 + m * 32 + c]      = T0;
    d_Tp[blk * 512 + m * 32 + c + 16] = T1;
    d_Gp[blk * 256 + t] = Greg;            // t = ma*16 + mb
    if (c == 0) d_Sp[blk * 16 + m] = Sacc;
}

// ---------- kernel B2: reduce partials -> dout, D, GN stat contributions ----------
__global__ __launch_bounds__(256) void k_dout() {
    __shared__ float s_S[16];
    __shared__ float s_dout[512];
    __shared__ double s_redd[16];
    int bb = blockIdx.x;
    int t = threadIdx.x;
    int b = bb >> 5;

    if (t < 16) {
        float s = 0.f;
        #pragma unroll
        for (int ch = 0; ch < 8; ch++) s += d_Sp[(bb * 8 + ch) * 16 + t];
        s_S[t] = s;
    }
    float Ta = 0.f, Tb = 0.f;
    #pragma unroll
    for (int ch = 0; ch < 8; ch++) {
        Ta += d_Tp[(bb * 8 + ch) * 512 + t];
        Tb += d_Tp[(bb * 8 + ch) * 512 + t + 256];
    }
    float Gf = 0.f;
    #pragma unroll
    for (int ch = 0; ch < 8; ch++) Gf += d_Gp[(bb * 8 + ch) * 256 + t];
    __syncthreads();

    int m1 = t >> 5, m2 = m1 + 8;
    float da = (Ta + d_cen[bb * 512 + t])       / (s_S[m1] + 1.f);
    float db = (Tb + d_cen[bb * 512 + t + 256]) / (s_S[m2] + 1.f);
    s_dout[t] = da; s_dout[t + 256] = db;
    d_dout[bb * 512 + t] = da;
    d_dout[bb * 512 + t + 256] = db;
    __syncthreads();

    int ma = t >> 4, mb = t & 15;
    float D = 0.f;
    #pragma unroll
    for (int c = 0; c < 32; c++) D += s_dout[ma * 32 + c] * s_dout[mb * 32 + c];

    double ds = (double)(da * s_S[m1] + db * s_S[m2]);  // sum(pre) contribution
    double d2 = (double)(Gf * D);                        // sumsq(pre) contribution
    #pragma unroll
    for (int o = 16; o; o >>= 1) {
        ds += __shfl_down_sync(0xffffffffu, ds, o);
        d2 += __shfl_down_sync(0xffffffffu, d2, o);
    }
    int wid = t >> 5, lane = t & 31;
    if (lane == 0) { s_redd[wid] = ds; s_redd[8 + wid] = d2; }
    __syncthreads();
    if (t == 0) {
        double a = 0.0, bq = 0.0;
        for (int w2 = 0; w2 < 8; w2++) { a += s_redd[w2]; bq += s_redd[8 + w2]; }
        atomicAdd(&d_gstats[b * 2], a);
        atomicAdd(&d_gstats[b * 2 + 1], bq);
    }
}

// ---------------- kernel D: fold GN scale into projection weights ----------------
__global__ void k_weff(const float* __restrict__ Wp, const float* __restrict__ gnw) {
    int idx = blockIdx.x * 256 + threadIdx.x;   // 262144
    int b = idx >> 16, oc = idx & 65535, c = idx & 255;
    double cnt = 4194304.0;
    double mu = d_gstats[b * 2] / cnt;
    double var = d_gstats[b * 2 + 1] / cnt - mu * mu;
    float inv = (float)(1.0 / sqrt(var + 1e-5));
    d_weff[idx] = Wp[oc] * inv * gnw[c];
}

// ---------------- kernel E: fold GN shift into projection bias ----------------
__global__ void k_beff(const float* __restrict__ Wp, const float* __restrict__ gnw,
                       const float* __restrict__ gnb, const float* __restrict__ bp) {
    int q = blockIdx.x * 8 + (threadIdx.x >> 5);   // 1024 warps
    int lane = threadIdx.x & 31;
    int b = q >> 8, o = q & 255;
    double cnt = 4194304.0;
    double mud = d_gstats[b * 2] / cnt;
    double var = d_gstats[b * 2 + 1] / cnt - mud * mud;
    float inv = (float)(1.0 / sqrt(var + 1e-5));
    float mu = (float)mud;
    float acc = 0.f;
    for (int c = lane; c < 256; c += 32) {
        float dc = gnb[c] - mu * inv * gnw[c];
        acc += dc * Wp[o * 256 + c];
    }
    #pragma unroll
    for (int off = 16; off; off >>= 1) acc += __shfl_down_sync(0xffffffffu, acc, off);
    if (lane == 0) d_beff[q] = bp[o] + acc;
}

// -------- kernel WD: WD[tile][o][e*16+m] = sum_c Weff[b][o][e*32+c]*dout[bb][m][c] --------
__global__ __launch_bounds__(256) void k_wd() {
    __shared__ float s_dout[512];
    int bb = blockIdx.x;
    int t = threadIdx.x;
    int b = bb >> 5, e = (bb >> 2) & 7;
    int tile = b * 4 + (bb & 3);            // (b, f1, f2)
    s_dout[t] = d_dout[bb * 512 + t];
    s_dout[t + 256] = d_dout[bb * 512 + t + 256];
    __syncthreads();
    const float* W = d_weff + b * 65536 + t * 256 + e * 32;   // row o=t
    float acc[16];
    #pragma unroll
    for (int m = 0; m < 16; m++) acc[m] = 0.f;
    #pragma unroll
    for (int c = 0; c < 32; c++) {
        float wv = W[c];
        #pragma unroll
        for (int m = 0; m < 16; m++) acc[m] += wv * s_dout[m * 32 + c];
    }
    float* dst = d_WD + tile * 32768 + t * 128 + e * 16;
    #pragma unroll
    for (int m = 0; m < 16; m++) dst[m] = f2tf(acc[m]);
}

// -------- kernel F: out[o][n] = silu(beff[o] + WD @ sim), tf32 m16n8k8 --------
// CTA 128o x 128n, 8 warps of 64o x 32n, K=128 in chunks of 32.
__global__ __launch_bounds__(256) void k_out(float* __restrict__ out) {
    __shared__ float SB[8960];              // Ws[128][36] | Ps[32][136]; epilogue Sout[64][132]
    float* Ws = SB;
    float* Ps = SB + 4608;
    int nb = blockIdx.x * 128;              // 32
    int ob = blockIdx.y * 128;              // 2
    int tile = blockIdx.z;                  // 16
    int b = tile >> 2, f1 = (tile >> 1) & 1, f2 = tile & 1;
    int t = threadIdx.x;
    int w = t >> 5, lane = t & 31;
    int g = lane >> 2, tid = lane & 3;
    int wo = w >> 2, wn = w & 3;            // warp: o = wo*64.., n = wn*32..
    const float* W = d_WD + tile * 32768;

    float acc[4][4][4];
    #pragma unroll
    for (int mt = 0; mt < 4; mt++)
        #pragma unroll
        for (int nt = 0; nt < 4; nt++)
            #pragma unroll
            for (int r = 0; r < 4; r++) acc[mt][nt][r] = 0.f;

    for (int k0 = 0; k0 < 128; k0 += 32) {
        #pragma unroll
        for (int r = 0; r < 4; r++) {       // Ws: 128o x 32k (already tf32-rounded)
            int idx = r * 256 + t;
            int o = idx >> 3, k4 = idx & 7;
            *(float4*)&Ws[o * 36 + k4 * 4] =
                *(const float4*)(W + (ob + o) * 128 + k0 + k4 * 4);
        }
        #pragma unroll
        for (int r = 0; r < 4; r++) {       // Ps: 32k x 128n
            int idx = r * 256 + t;
            int k = idx >> 5, n4 = idx & 31;
            int q = k0 + k;                 // q = e*16 + m
            int bbq = b * 32 + (q >> 4) * 4 + f1 * 2 + f2;
            const float* srow = d_sim + (size_t)bbq * 65536 + (q & 15) * 4096 + nb;
            *(float4*)&Ps[k * 136 + n4 * 4] = *(const float4*)(srow + n4 * 4);
        }
        __syncthreads();
        #pragma unroll
        for (int kt = 0; kt < 4; kt++) {    // m16n8k8: 4 k-steps of 8
            unsigned a0[4], a1[4], a2[4], a3[4], b0[4], b1[4];
            #pragma unroll
            for (int mt = 0; mt < 4; mt++) {
                int row = wo * 64 + mt * 16;
                a0[mt] = __float_as_uint(Ws[(row + g) * 36 + kt * 8 + tid]);
                a1[mt] = __float_as_uint(Ws[(row + g + 8) * 36 + kt * 8 + tid]);
                a2[mt] = __float_as_uint(Ws[(row + g) * 36 + kt * 8 + tid + 4]);
                a3[mt] = __float_as_uint(Ws[(row + g + 8) * 36 + kt * 8 + tid + 4]);
            }
            #pragma unroll
            for (int nt = 0; nt < 4; nt++) {
                int col = wn * 32 + nt * 8 + g;
                b0[nt] = __float_as_uint(Ps[(kt * 8 + tid) * 136 + col]);
                b1[nt] = __float_as_uint(Ps[(kt * 8 + tid + 4) * 136 + col]);
            }
            #pragma unroll
            for (int mt = 0; mt < 4; mt++)
                #pragma unroll
                for (int nt = 0; nt < 4; nt++)
                    asm volatile(
                        "mma.sync.aligned.m16n8k8.row.col.f32.tf32.tf32.f32 "
                        "{%0,%1,%2,%3}, {%4,%5,%6,%7}, {%8,%9}, {%0,%1,%2,%3};"
                        : "+f"(acc[mt][nt][0]), "+f"(acc[mt][nt][1]),
                          "+f"(acc[mt][nt][2]), "+f"(acc[mt][nt][3])
                        : "r"(a0[mt]), "r"(a1[mt]), "r"(a2[mt]), "r"(a3[mt]),
                          "r"(b0[nt]), "r"(b1[nt]));
        }
        __syncthreads();
    }

    // epilogue: two o-halves via smem for coalesced float4 stores
    float* Sout = SB;                       // [64][132]
    #pragma unroll
    for (int h = 0; h < 2; h++) {
        if (wo == h) {
            #pragma unroll
            for (int mt = 0; mt < 4; mt++) {
                int r0 = mt * 16 + g;
                #pragma unroll
                for (int nt = 0; nt < 4; nt++) {
                    int col = wn * 32 + nt * 8 + 2 * tid;
                    Sout[r0 * 132 + col]           = acc[mt][nt][0];
                    Sout[r0 * 132 + col + 1]       = acc[mt][nt][1];
                    Sout[(r0 + 8) * 132 + col]     = acc[mt][nt][2];
                    Sout[(r0 + 8) * 132 + col + 1] = acc[mt][nt][3];
                }
            }
        }
        __syncthreads();
        #pragma unroll
        for (int r = 0; r < 8; r++) {
            int idx = r * 256 + t;          // 2048 float4
            int row = idx >> 5, n4 = idx & 31;
            int o = ob + h * 64 + row;
            float bias = d_beff[b * 256 + o];
            float4 v = *(const float4*)&Sout[row * 132 + n4 * 4];
            float z0 = v.x + bias, z1 = v.y + bias, z2 = v.z + bias, z3 = v.w + bias;
            float4 rr = make_float4(z0 * sigmoidf(z0), z1 * sigmoidf(z1),
                                    z2 * sigmoidf(z2), z3 * sigmoidf(z3));
            int nloc = nb + n4 * 4;
            int irow = nloc >> 6, jcol = nloc & 63;
            float* orow = out + (((size_t)(b * 256 + o)) << 14)
                              + (f1 * 64 + irow) * 128 + f2 * 64 + jcol;
            *(float4*)orow = rr;
        }
        __syncthreads();
    }
}

// ---------------- launch ----------------
extern "C" void kernel_launch(void* const* d_in, const int* in_sizes, int n_in,
                              void* d_out, int out_size) {
    const float* x     = (const float*)d_in[0];
    const float* xyz   = (const float*)d_in[1];
    // d_in[2]=Wv, d_in[3]=bv : dead code (split path multiplied by zero mask)
    const float* Wproj = (const float*)d_in[4];
    const float* bproj = (const float*)d_in[5];
    const float* gnw   = (const float*)d_in[6];
    const float* gnb   = (const float*)d_in[7];
    const float* sa    = (const float*)d_in[8];
    const float* sb    = (const float*)d_in[9];
    float* out = (float*)d_out;

    cudaFuncSetAttribute(k_simT, cudaFuncAttributeMaxDynamicSharedMemorySize, SMEMT);

    k_centers<<<8192, 256>>>(x);
    k_ncen<<<256, 256>>>();
    k_geo<<<1, 256>>>(xyz);
    k_geo2<<<dim3(16, 64), 256>>>(xyz, sa, sb);
    k_simT<<<1024, 256, SMEMT>>>(x, sa, sb);
    k_dout<<<128, 256>>>();
    k_weff<<<1024, 256>>>(Wproj, gnw);
    k_beff<<<128, 256>>>(Wproj, gnw, gnb, bproj);
    k_wd<<<128, 256>>>();
    k_out<<<dim3(32, 2, 16), 256>>>(out);
}

// round 11
// speedup vs baseline: 1.1105x; 1.1105x over previous
#include <cuda_runtime.h>
#include <math.h>

// x: (4,256,128,128)  xyz: (4,3,128,128)
// folded blocks: NB=128 (b*32 + e*4 + f1*2 + f2), c=32, tile 64x64, M=16 centers
#define NB 128
#define MCNT 16

// ---------------- scratch (static __device__, no allocation) ----------------
__device__ float  d_cen [NB*512];         // pooled centers (unnormalized)
__device__ float  d_ncen[NB*512];         // l2-normalized centers
__device__ float  d_ngeo[16*16*4];        // normalized xyz centers, padded to 4
__device__ float  d_sgeo2[16*16*4096];    // sigmoid(geo)^2 table  [g][m][n]  (4 MB)
__device__ float  d_sim [NB*16*4096];     // 33.5 MB sim cache (tf32-rounded values)
__device__ float  d_Tp  [1024*512];       // partial T = sim@x  (per bb-chunk)
__device__ float  d_Sp  [1024*16];        // partial rowsum(sim)
__device__ float  d_Gp  [1024*256];       // partial Gram(sim)
__device__ float  d_dout[NB*512];         // dense_out (16m x 32c per bb)
__device__ double d_gstats[8];            // per-batch sum, sumsq
__device__ float  d_beff[4*256];          // GN-folded projection bias
__device__ float  d_WD  [16*256*128];     // fused weights (tf32-rounded)

__device__ __forceinline__ float sigmoidf(float z) { return 1.f / (1.f + __expf(-z)); }
__device__ __forceinline__ float f2tf(float f) {
    unsigned u; asm("cvt.rna.tf32.f32 %0, %1;" : "=r"(u) : "f"(f));
    return __uint_as_float(u);
}

// ---------------- kernel A: pooled centers, warp per (bb,m,c), float4 ----------------
__global__ void k_centers(const float* __restrict__ x) {
    int w = blockIdx.x * 8 + (threadIdx.x >> 5);   // 65536 warps
    int lane = threadIdx.x & 31;
    int bb = w >> 9; int rem = w & 511; int m = rem >> 5; int c = rem & 31;
    int b = bb >> 5, e = (bb >> 2) & 7, f1 = (bb >> 1) & 1, f2 = bb & 1;
    int pi = m >> 2, pj = m & 3;
    const float* xp = x + (((size_t)(b * 256 + e * 32 + c)) << 14)
                        + (f1 * 64 + pi * 16) * 128 + f2 * 64 + pj * 16;
    float acc = 0.f;
    #pragma unroll
    for (int r = 0; r < 2; r++) {
        int idx = r * 32 + lane;              // 0..63 float4s
        int ii = idx >> 2, jj4 = idx & 3;
        float4 v = *(const float4*)(xp + ii * 128 + jj4 * 4);
        acc += (v.x + v.y) + (v.z + v.w);
    }
    #pragma unroll
    for (int o = 16; o; o >>= 1) acc += __shfl_down_sync(0xffffffffu, acc, o);
    if (lane == 0) d_cen[w] = acc * (1.f / 256.f);
}

// ---------------- kernel A2: normalize centers, warp per (bb,m) ----------------
__global__ void k_ncen() {
    int q = blockIdx.x * 8 + (threadIdx.x >> 5);   // 2048 warps
    int c = threadIdx.x & 31;
    float v = d_cen[q * 32 + c];
    float ss = v * v;
    #pragma unroll
    for (int o = 16; o; o >>= 1) ss += __shfl_xor_sync(0xffffffffu, ss, o);
    float inv = 1.f / fmaxf(sqrtf(ss), 1e-12f);
    d_ncen[q * 32 + c] = v * inv;
}

// ---------------- kernel A3: normalized xyz centers + zero stats ----------------
__global__ void k_geo(const float* __restrict__ xyz) {
    int t = threadIdx.x;
    if (t < 8) d_gstats[t] = 0.0;
    int g = t >> 4, m = t & 15;
    int b = g >> 2, f1 = (g >> 1) & 1, f2 = g & 1;
    int pi = m >> 2, pj = m & 3;
    const float* base = xyz + (((size_t)(b * 3)) << 14)
                            + (f1 * 64 + pi * 16) * 128 + f2 * 64 + pj * 16;
    float s0 = 0.f, s1 = 0.f, s2 = 0.f;
    for (int ii = 0; ii < 16; ii++)
        for (int jj = 0; jj < 16; jj++) {
            int off = ii * 128 + jj;
            s0 += base[off];
            s1 += base[off + 16384];
            s2 += base[off + 32768];
        }
    s0 *= (1.f / 256.f); s1 *= (1.f / 256.f); s2 *= (1.f / 256.f);
    float inv = 1.f / fmaxf(sqrtf(s0 * s0 + s1 * s1 + s2 * s2), 1e-12f);
    int o = (g * 16 + m) * 4;
    d_ngeo[o] = s0 * inv; d_ngeo[o + 1] = s1 * inv; d_ngeo[o + 2] = s2 * inv; d_ngeo[o + 3] = 0.f;
}

// ---------------- kernel A4: sim_geo^2 table [g][m][n], grid (16 g, 64 i) ----------------
__global__ void k_geo2(const float* __restrict__ xyz,
                       const float* __restrict__ salpha, const float* __restrict__ sbeta) {
    int g = blockIdx.x, i = blockIdx.y;
    int t = threadIdx.x;
    int j = t & 63, mg = t >> 6;                 // 4 m-groups of 4
    int bg = g >> 2, f1 = (g >> 1) & 1, f2 = g & 1;
    float alpha = salpha[0], beta = sbeta[0];
    const float* base = xyz + (((size_t)(bg * 3)) << 14) + (f1 * 64 + i) * 128 + f2 * 64 + j;
    float p0 = base[0], p1 = base[16384], p2 = base[32768];
    float inv = 1.f / fmaxf(sqrtf(p0 * p0 + p1 * p1 + p2 * p2), 1e-12f);
    p0 *= inv; p1 *= inv; p2 *= inv;
    #pragma unroll
    for (int mm = 0; mm < 4; mm++) {
        int m = mg * 4 + mm;
        const float* ng = d_ngeo + (g * 16 + m) * 4;
        float gd = ng[0] * p0 + ng[1] * p1 + ng[2] * p2;
        float sg = sigmoidf(beta + alpha * gd);
        d_sgeo2[(g * 16 + m) * 4096 + i * 64 + j] = sg * sg;
    }
}

// ------- fused kernel: sim (phase A) + T/S/G reduction (phase B), big smem -------
// CTA per (bb, 8-row chunk). 3 syncs total: load | norms | sim->phase B.
#define XS 516
#define SMEMT ((32*XS + 16*XS + 512 + 512) * 4)
__global__ __launch_bounds__(256) void k_simT(const float* __restrict__ x,
                                              const float* __restrict__ salpha,
                                              const float* __restrict__ sbeta) {
    extern __shared__ float SB[];
    float* s_x    = SB;                   // [32][XS]
    float* s_sim  = SB + 32 * XS;         // [16][XS]
    float* s_ncen = SB + 48 * XS;         // [512]
    float* s_inv  = SB + 48 * XS + 512;   // [512]

    int blk = blockIdx.x;                  // 0..1023
    int bb = blk >> 3, chunk = blk & 7;
    int t = threadIdx.x;
    int m = t >> 4, jq = t & 15, j0 = jq * 4;
    int b = bb >> 5, e = (bb >> 2) & 7, f1 = (bb >> 1) & 1, f2 = bb & 1;
    int g = bb & 15;        // reference's tile() quirk: geo block = bb % 16
    float alpha = salpha[0], beta = sbeta[0];

    s_ncen[t]       = d_ncen[bb * 512 + t];
    s_ncen[t + 256] = d_ncen[bb * 512 + t + 256];

    const float* xb = x + (((size_t)(b * 256 + e * 32)) << 14) + (f1 * 64) * 128 + f2 * 64;
    float* simb = d_sim + (size_t)bb * 65536 + m * 4096;
    const float* sgb = d_sgeo2 + (g * 16 + m) * 4096;

    // ---- load phase: whole 32x512 x slab, front-batched LDGs, one sync ----
    #pragma unroll
    for (int r = 0; r < 16; r++) {
        int idx = r * 256 + t;             // 4096 float4
        int c = idx >> 7, rest = idx & 127;
        int ir = rest >> 4, j4 = rest & 15;
        *(float4*)&s_x[c * XS + ir * 64 + j4 * 4] =
            *(const float4*)(xb + c * 16384 + (chunk * 8 + ir) * 128 + j4 * 4);
    }
    __syncthreads();

    // ---- norm phase: 512 columns / 256 threads (2 each), conflict-free scalar walk ----
    {
        float ss0 = 0.f, ss1 = 0.f;
        #pragma unroll 8
        for (int c = 0; c < 32; c++) {
            float v0 = s_x[c * XS + t];
            float v1 = s_x[c * XS + t + 256];
            ss0 += v0 * v0; ss1 += v1 * v1;
        }
        s_inv[t]       = 1.f / fmaxf(sqrtf(ss0), 1e-12f);
        s_inv[t + 256] = 1.f / fmaxf(sqrtf(ss1), 1e-12f);
    }
    __syncthreads();

    // ---- phase A: sim rows, no syncs between iters ----
    #pragma unroll 2
    for (int ir = 0; ir < 8; ir++) {
        int i = chunk * 8 + ir;
        float d0 = 0.f, d1 = 0.f, d2 = 0.f, d3 = 0.f;
        #pragma unroll
        for (int c4 = 0; c4 < 8; c4++) {
            float4 nc = *(const float4*)&s_ncen[m * 32 + c4 * 4];
            float4 xa = *(const float4*)&s_x[(c4 * 4 + 0) * XS + ir * 64 + j0];
            float4 xb_ = *(const float4*)&s_x[(c4 * 4 + 1) * XS + ir * 64 + j0];
            float4 xc = *(const float4*)&s_x[(c4 * 4 + 2) * XS + ir * 64 + j0];
            float4 xd = *(const float4*)&s_x[(c4 * 4 + 3) * XS + ir * 64 + j0];
            d0 += nc.x * xa.x + nc.y * xb_.x + nc.z * xc.x + nc.w * xd.x;
            d1 += nc.x * xa.y + nc.y * xb_.y + nc.z * xc.y + nc.w * xd.y;
            d2 += nc.x * xa.z + nc.y * xb_.z + nc.z * xc.z + nc.w * xd.z;
            d3 += nc.x * xa.w + nc.y * xb_.w + nc.z * xc.w + nc.w * xd.w;
        }
        float4 sg2 = *(const float4*)(sgb + i * 64 + j0);
        float i0 = s_inv[ir * 64 + j0];
        float i1 = s_inv[ir * 64 + j0 + 1];
        float i2 = s_inv[ir * 64 + j0 + 2];
        float i3 = s_inv[ir * 64 + j0 + 3];
        float s0 = f2tf(sigmoidf(beta + alpha * d0 * i0) * sg2.x);
        float s1 = f2tf(sigmoidf(beta + alpha * d1 * i1) * sg2.y);
        float s2 = f2tf(sigmoidf(beta + alpha * d2 * i2) * sg2.z);
        float s3 = f2tf(sigmoidf(beta + alpha * d3 * i3) * sg2.w);
        float4 sv = make_float4(s0, s1, s2, s3);
        *(float4*)&s_sim[m * XS + ir * 64 + j0] = sv;
        *(float4*)(simb + i * 64 + j0) = sv;
    }
    __syncthreads();

    // ---- phase B: T = sim@x^T, S = rowsum(sim), G = sim@sim^T from resident tiles ----
    int c = jq;                            // T roles (m, c) and (m, c+16); G roles (m, c)
    float T0 = 0.f, T1 = 0.f, Greg = 0.f, Sacc = 0.f;
    #pragma unroll 4
    for (int k4 = 0; k4 < 128; k4++) {
        float4 a  = *(const float4*)&s_sim[m * XS + k4 * 4];
        float4 bq = *(const float4*)&s_sim[c * XS + k4 * 4];
        float4 xa = *(const float4*)&s_x[c * XS + k4 * 4];
        float4 xc = *(const float4*)&s_x[(c + 16) * XS + k4 * 4];
        T0 += a.x * xa.x + a.y * xa.y + a.z * xa.z + a.w * xa.w;
        T1 += a.x * xc.x + a.y * xc.y + a.z * xc.z + a.w * xc.w;
        Greg += a.x * bq.x + a.y * bq.y + a.z * bq.z + a.w * bq.w;
        if (c == 0) Sacc += (a.x + a.y) + (a.z + a.w);
    }
    d_Tp[blk * 512 + m * 32 + c]      = T0;
    d_Tp[blk * 512 + m * 32 + c + 16] = T1;
    d_Gp[blk * 256 + t] = Greg;            // t = ma*16 + mb
    if (c == 0) d_Sp[blk * 16 + m] = Sacc;
}

// ---------- kernel B2: reduce partials -> dout, D, GN stat contributions ----------
__global__ __launch_bounds__(256) void k_dout() {
    __shared__ float s_S[16];
    __shared__ float s_dout[512];
    __shared__ double s_redd[16];
    int bb = blockIdx.x;
    int t = threadIdx.x;
    int b = bb >> 5;

    if (t < 16) {
        float s = 0.f;
        #pragma unroll
        for (int ch = 0; ch < 8; ch++) s += d_Sp[(bb * 8 + ch) * 16 + t];
        s_S[t] = s;
    }
    float Ta = 0.f, Tb = 0.f;
    #pragma unroll
    for (int ch = 0; ch < 8; ch++) {
        Ta += d_Tp[(bb * 8 + ch) * 512 + t];
        Tb += d_Tp[(bb * 8 + ch) * 512 + t + 256];
    }
    float Gf = 0.f;
    #pragma unroll
    for (int ch = 0; ch < 8; ch++) Gf += d_Gp[(bb * 8 + ch) * 256 + t];
    __syncthreads();

    int m1 = t >> 5, m2 = m1 + 8;
    float da = (Ta + d_cen[bb * 512 + t])       / (s_S[m1] + 1.f);
    float db = (Tb + d_cen[bb * 512 + t + 256]) / (s_S[m2] + 1.f);
    s_dout[t] = da; s_dout[t + 256] = db;
    d_dout[bb * 512 + t] = da;
    d_dout[bb * 512 + t + 256] = db;
    __syncthreads();

    int ma = t >> 4, mb = t & 15;
    float D = 0.f;
    #pragma unroll
    for (int c = 0; c < 32; c++) D += s_dout[ma * 32 + c] * s_dout[mb * 32 + c];

    double ds = (double)(da * s_S[m1] + db * s_S[m2]);  // sum(pre) contribution
    double d2 = (double)(Gf * D);                        // sumsq(pre) contribution
    #pragma unroll
    for (int o = 16; o; o >>= 1) {
        ds += __shfl_down_sync(0xffffffffu, ds, o);
        d2 += __shfl_down_sync(0xffffffffu, d2, o);
    }
    int wid = t >> 5, lane = t & 31;
    if (lane == 0) { s_redd[wid] = ds; s_redd[8 + wid] = d2; }
    __syncthreads();
    if (t == 0) {
        double a = 0.0, bq = 0.0;
        for (int w2 = 0; w2 < 8; w2++) { a += s_redd[w2]; bq += s_redd[8 + w2]; }
        atomicAdd(&d_gstats[b * 2], a);
        atomicAdd(&d_gstats[b * 2 + 1], bq);
    }
}

// ---------------- kernel E: fold GN shift into projection bias ----------------
__global__ void k_beff(const float* __restrict__ Wp, const float* __restrict__ gnw,
                       const float* __restrict__ gnb, const float* __restrict__ bp) {
    int q = blockIdx.x * 8 + (threadIdx.x >> 5);   // 1024 warps
    int lane = threadIdx.x & 31;
    int b = q >> 8, o = q & 255;
    double cnt = 4194304.0;
    double mud = d_gstats[b * 2] / cnt;
    double var = d_gstats[b * 2 + 1] / cnt - mud * mud;
    float inv = (float)(1.0 / sqrt(var + 1e-5));
    float mu = (float)mud;
    float acc = 0.f;
    for (int c = lane; c < 256; c += 32) {
        float dc = gnb[c] - mu * inv * gnw[c];
        acc += dc * Wp[o * 256 + c];
    }
    #pragma unroll
    for (int off = 16; off; off >>= 1) acc += __shfl_down_sync(0xffffffffu, acc, off);
    if (lane == 0) d_beff[q] = bp[o] + acc;
}

// -------- kernel WD: WD[tile][o][e*16+m] = inv_b * sum_c Wp[o][e*32+c]*gnw[e*32+c]*dout[bb][m][c] --------
__global__ __launch_bounds__(256) void k_wd(const float* __restrict__ Wp,
                                            const float* __restrict__ gnw) {
    __shared__ float s_dout[512];          // dout * gnw (per-channel)
    int bb = blockIdx.x;
    int t = threadIdx.x;
    int b = bb >> 5, e = (bb >> 2) & 7;
    int tile = b * 4 + (bb & 3);            // (b, f1, f2)
    // load dout scaled by gnw[e*32 + c]
    {
        int c0 = t & 31;
        float gw = gnw[e * 32 + c0];
        s_dout[t]       = d_dout[bb * 512 + t] * gw;
        s_dout[t + 256] = d_dout[bb * 512 + t + 256] * gw;
    }
    double cnt = 4194304.0;
    double mu = d_gstats[b * 2] / cnt;
    double var = d_gstats[b * 2 + 1] / cnt - mu * mu;
    float inv = (float)(1.0 / sqrt(var + 1e-5));
    __syncthreads();
    const float* W = Wp + t * 256 + e * 32;   // row o=t
    float acc[16];
    #pragma unroll
    for (int m = 0; m < 16; m++) acc[m] = 0.f;
    #pragma unroll
    for (int c = 0; c < 32; c++) {
        float wv = W[c];
        #pragma unroll
        for (int m = 0; m < 16; m++) acc[m] += wv * s_dout[m * 32 + c];
    }
    float* dst = d_WD + tile * 32768 + t * 128 + e * 16;
    #pragma unroll
    for (int m = 0; m < 16; m++) dst[m] = f2tf(acc[m] * inv);
}

// -------- kernel F: out[o][n] = silu(beff[o] + WD @ sim), tf32 m16n8k8 --------
// CTA 128o x 128n, 8 warps of 64o x 32n, K=128 in chunks of 32.
__global__ __launch_bounds__(256) void k_out(float* __restrict__ out) {
    __shared__ float SB[8960];              // Ws[128][36] | Ps[32][136]; epilogue Sout[64][132]
    float* Ws = SB;
    float* Ps = SB + 4608;
    int nb = blockIdx.x * 128;              // 32
    int ob = blockIdx.y * 128;              // 2
    int tile = blockIdx.z;                  // 16
    int b = tile >> 2, f1 = (tile >> 1) & 1, f2 = tile & 1;
    int t = threadIdx.x;
    int w = t >> 5, lane = t & 31;
    int g = lane >> 2, tid = lane & 3;
    int wo = w >> 2, wn = w & 3;            // warp: o = wo*64.., n = wn*32..
    const float* W = d_WD + tile * 32768;

    float acc[4][4][4];
    #pragma unroll
    for (int mt = 0; mt < 4; mt++)
        #pragma unroll
        for (int nt = 0; nt < 4; nt++)
            #pragma unroll
            for (int r = 0; r < 4; r++) acc[mt][nt][r] = 0.f;

    for (int k0 = 0; k0 < 128; k0 += 32) {
        #pragma unroll
        for (int r = 0; r < 4; r++) {       // Ws: 128o x 32k (already tf32-rounded)
            int idx = r * 256 + t;
            int o = idx >> 3, k4 = idx & 7;
            *(float4*)&Ws[o * 36 + k4 * 4] =
                *(const float4*)(W + (ob + o) * 128 + k0 + k4 * 4);
        }
        #pragma unroll
        for (int r = 0; r < 4; r++) {       // Ps: 32k x 128n
            int idx = r * 256 + t;
            int k = idx >> 5, n4 = idx & 31;
            int q = k0 + k;                 // q = e*16 + m
            int bbq = b * 32 + (q >> 4) * 4 + f1 * 2 + f2;
            const float* srow = d_sim + (size_t)bbq * 65536 + (q & 15) * 4096 + nb;
            *(float4*)&Ps[k * 136 + n4 * 4] = *(const float4*)(srow + n4 * 4);
        }
        __syncthreads();
        #pragma unroll
        for (int kt = 0; kt < 4; kt++) {    // m16n8k8: 4 k-steps of 8
            unsigned a0[4], a1[4], a2[4], a3[4], b0[4], b1[4];
            #pragma unroll
            for (int mt = 0; mt < 4; mt++) {
                int row = wo * 64 + mt * 16;
                a0[mt] = __float_as_uint(Ws[(row + g) * 36 + kt * 8 + tid]);
                a1[mt] = __float_as_uint(Ws[(row + g + 8) * 36 + kt * 8 + tid]);
                a2[mt] = __float_as_uint(Ws[(row + g) * 36 + kt * 8 + tid + 4]);
                a3[mt] = __float_as_uint(Ws[(row + g + 8) * 36 + kt * 8 + tid + 4]);
            }
            #pragma unroll
            for (int nt = 0; nt < 4; nt++) {
                int col = wn * 32 + nt * 8 + g;
                b0[nt] = __float_as_uint(Ps[(kt * 8 + tid) * 136 + col]);
                b1[nt] = __float_as_uint(Ps[(kt * 8 + tid + 4) * 136 + col]);
            }
            #pragma unroll
            for (int mt = 0; mt < 4; mt++)
                #pragma unroll
                for (int nt = 0; nt < 4; nt++)
                    asm volatile(
                        "mma.sync.aligned.m16n8k8.row.col.f32.tf32.tf32.f32 "
                        "{%0,%1,%2,%3}, {%4,%5,%6,%7}, {%8,%9}, {%0,%1,%2,%3};"
                        : "+f"(acc[mt][nt][0]), "+f"(acc[mt][nt][1]),
                          "+f"(acc[mt][nt][2]), "+f"(acc[mt][nt][3])
                        : "r"(a0[mt]), "r"(a1[mt]), "r"(a2[mt]), "r"(a3[mt]),
                          "r"(b0[nt]), "r"(b1[nt]));
        }
        __syncthreads();
    }

    // epilogue: two o-halves via smem for coalesced float4 stores
    float* Sout = SB;                       // [64][132]
    #pragma unroll
    for (int h = 0; h < 2; h++) {
        if (wo == h) {
            #pragma unroll
            for (int mt = 0; mt < 4; mt++) {
                int r0 = mt * 16 + g;
                #pragma unroll
                for (int nt = 0; nt < 4; nt++) {
                    int col = wn * 32 + nt * 8 + 2 * tid;
                    Sout[r0 * 132 + col]           = acc[mt][nt][0];
                    Sout[r0 * 132 + col + 1]       = acc[mt][nt][1];
                    Sout[(r0 + 8) * 132 + col]     = acc[mt][nt][2];
                    Sout[(r0 + 8) * 132 + col + 1] = acc[mt][nt][3];
                }
            }
        }
        __syncthreads();
        #pragma unroll
        for (int r = 0; r < 8; r++) {
            int idx = r * 256 + t;          // 2048 float4
            int row = idx >> 5, n4 = idx & 31;
            int o = ob + h * 64 + row;
            float bias = d_beff[b * 256 + o];
            float4 v = *(const float4*)&Sout[row * 132 + n4 * 4];
            float z0 = v.x + bias, z1 = v.y + bias, z2 = v.z + bias, z3 = v.w + bias;
            float4 rr = make_float4(z0 * sigmoidf(z0), z1 * sigmoidf(z1),
                                    z2 * sigmoidf(z2), z3 * sigmoidf(z3));
            int nloc = nb + n4 * 4;
            int irow = nloc >> 6, jcol = nloc & 63;
            float* orow = out + (((size_t)(b * 256 + o)) << 14)
                              + (f1 * 64 + irow) * 128 + f2 * 64 + jcol;
            *(float4*)orow = rr;
        }
        __syncthreads();
    }
}

// ---------------- launch ----------------
extern "C" void kernel_launch(void* const* d_in, const int* in_sizes, int n_in,
                              void* d_out, int out_size) {
    const float* x     = (const float*)d_in[0];
    const float* xyz   = (const float*)d_in[1];
    // d_in[2]=Wv, d_in[3]=bv : dead code (split path multiplied by zero mask)
    const float* Wproj = (const float*)d_in[4];
    const float* bproj = (const float*)d_in[5];
    const float* gnw   = (const float*)d_in[6];
    const float* gnb   = (const float*)d_in[7];
    const float* sa    = (const float*)d_in[8];
    const float* sb    = (const float*)d_in[9];
    float* out = (float*)d_out;

    cudaFuncSetAttribute(k_simT, cudaFuncAttributeMaxDynamicSharedMemorySize, SMEMT);

    k_centers<<<8192, 256>>>(x);
    k_ncen<<<256, 256>>>();
    k_geo<<<1, 256>>>(xyz);
    k_geo2<<<dim3(16, 64), 256>>>(xyz, sa, sb);
    k_simT<<<1024, 256, SMEMT>>>(x, sa, sb);
    k_dout<<<128, 256>>>();
    k_beff<<<128, 256>>>(Wproj, gnw, gnb, bproj);
    k_wd<<<128, 256>>>(Wproj, gnw);
    k_out<<<dim3(32, 2, 16), 256>>>(out);
}

// round 12
// speedup vs baseline: 1.2310x; 1.1085x over previous
#include <cuda_runtime.h>
#include <math.h>

// x: (4,256,128,128)  xyz: (4,3,128,128)
// folded blocks: NB=128 (b*32 + e*4 + f1*2 + f2), c=32, tile 64x64, M=16 centers
#define NB 128
#define MCNT 16

// ---------------- scratch (static __device__, no allocation) ----------------
__device__ float  d_cen [NB*512];         // pooled centers (unnormalized)
__device__ float  d_ncen[NB*512];         // l2-normalized centers
__device__ float  d_ngeo[16*16*4];        // normalized xyz centers, padded to 4
__device__ float  d_sgeo2[16*16*4096];    // sigmoid(geo)^2 table  [g][m][n]  (4 MB)
__device__ float  d_sim [NB*16*4096];     // 33.5 MB sim cache (tf32-rounded values)
__device__ float  d_Tp  [1024*512];       // partial T = sim@x  (per bb-chunk)
__device__ float  d_Sp  [1024*16];        // partial rowsum(sim)
__device__ float  d_Gp  [1024*256];       // partial Gram(sim)
__device__ float  d_dout[NB*512];         // dense_out (16m x 32c per bb)
__device__ double d_gstats[8];            // per-batch sum, sumsq
__device__ float  d_beff[4*256];          // GN-folded projection bias
__device__ float  d_WD  [16*256*128];     // fused weights (tf32-rounded)

__device__ __forceinline__ float sigmoidf(float z) { return 1.f / (1.f + __expf(-z)); }
__device__ __forceinline__ float f2tf(float f) {
    unsigned u; asm("cvt.rna.tf32.f32 %0, %1;" : "=r"(u) : "f"(f));
    return __uint_as_float(u);
}

// ---------------- kernel A: pooled centers, warp per (bb,m,c), float4 ----------------
__global__ void k_centers(const float* __restrict__ x) {
    int w = blockIdx.x * 8 + (threadIdx.x >> 5);   // 65536 warps
    int lane = threadIdx.x & 31;
    int bb = w >> 9; int rem = w & 511; int m = rem >> 5; int c = rem & 31;
    int b = bb >> 5, e = (bb >> 2) & 7, f1 = (bb >> 1) & 1, f2 = bb & 1;
    int pi = m >> 2, pj = m & 3;
    const float* xp = x + (((size_t)(b * 256 + e * 32 + c)) << 14)
                        + (f1 * 64 + pi * 16) * 128 + f2 * 64 + pj * 16;
    float acc = 0.f;
    #pragma unroll
    for (int r = 0; r < 2; r++) {
        int idx = r * 32 + lane;              // 0..63 float4s
        int ii = idx >> 2, jj4 = idx & 3;
        float4 v = *(const float4*)(xp + ii * 128 + jj4 * 4);
        acc += (v.x + v.y) + (v.z + v.w);
    }
    #pragma unroll
    for (int o = 16; o; o >>= 1) acc += __shfl_down_sync(0xffffffffu, acc, o);
    if (lane == 0) d_cen[w] = acc * (1.f / 256.f);
}

// ---------------- kernel A2: normalize centers, warp per (bb,m) ----------------
__global__ void k_ncen() {
    int q = blockIdx.x * 8 + (threadIdx.x >> 5);   // 2048 warps
    int c = threadIdx.x & 31;
    float v = d_cen[q * 32 + c];
    float ss = v * v;
    #pragma unroll
    for (int o = 16; o; o >>= 1) ss += __shfl_xor_sync(0xffffffffu, ss, o);
    float inv = 1.f / fmaxf(sqrtf(ss), 1e-12f);
    d_ncen[q * 32 + c] = v * inv;
}

// ---------------- kernel A3: normalized xyz centers + zero stats ----------------
__global__ void k_geo(const float* __restrict__ xyz) {
    int t = threadIdx.x;
    if (t < 8) d_gstats[t] = 0.0;
    int g = t >> 4, m = t & 15;
    int b = g >> 2, f1 = (g >> 1) & 1, f2 = g & 1;
    int pi = m >> 2, pj = m & 3;
    const float* base = xyz + (((size_t)(b * 3)) << 14)
                            + (f1 * 64 + pi * 16) * 128 + f2 * 64 + pj * 16;
    float s0 = 0.f, s1 = 0.f, s2 = 0.f;
    for (int ii = 0; ii < 16; ii++)
        for (int jj = 0; jj < 16; jj++) {
            int off = ii * 128 + jj;
            s0 += base[off];
            s1 += base[off + 16384];
            s2 += base[off + 32768];
        }
    s0 *= (1.f / 256.f); s1 *= (1.f / 256.f); s2 *= (1.f / 256.f);
    float inv = 1.f / fmaxf(sqrtf(s0 * s0 + s1 * s1 + s2 * s2), 1e-12f);
    int o = (g * 16 + m) * 4;
    d_ngeo[o] = s0 * inv; d_ngeo[o + 1] = s1 * inv; d_ngeo[o + 2] = s2 * inv; d_ngeo[o + 3] = 0.f;
}

// ---------------- kernel A4: sim_geo^2 table [g][m][n], grid (16 g, 64 i) ----------------
__global__ void k_geo2(const float* __restrict__ xyz,
                       const float* __restrict__ salpha, const float* __restrict__ sbeta) {
    int g = blockIdx.x, i = blockIdx.y;
    int t = threadIdx.x;
    int j = t & 63, mg = t >> 6;                 // 4 m-groups of 4
    int bg = g >> 2, f1 = (g >> 1) & 1, f2 = g & 1;
    float alpha = salpha[0], beta = sbeta[0];
    const float* base = xyz + (((size_t)(bg * 3)) << 14) + (f1 * 64 + i) * 128 + f2 * 64 + j;
    float p0 = base[0], p1 = base[16384], p2 = base[32768];
    float inv = 1.f / fmaxf(sqrtf(p0 * p0 + p1 * p1 + p2 * p2), 1e-12f);
    p0 *= inv; p1 *= inv; p2 *= inv;
    #pragma unroll
    for (int mm = 0; mm < 4; mm++) {
        int m = mg * 4 + mm;
        const float* ng = d_ngeo + (g * 16 + m) * 4;
        float gd = ng[0] * p0 + ng[1] * p1 + ng[2] * p2;
        float sg = sigmoidf(beta + alpha * gd);
        d_sgeo2[(g * 16 + m) * 4096 + i * 64 + j] = sg * sg;
    }
}

// ------- fused kernel: sim (phase A) + T/S/G reduction (phase B), big smem -------
// CTA per (bb, 8-row chunk). 3 syncs. Crossbar-optimized lane maps.
#define XS 516
#define SMEMT ((48*XS + 512) * 4)
__global__ __launch_bounds__(256) void k_simT(const float* __restrict__ x,
                                              const float* __restrict__ salpha,
                                              const float* __restrict__ sbeta) {
    extern __shared__ float SB[];
    float* s_x    = SB;                   // [32][XS]
    float* s_sim  = SB + 32 * XS;         // [16][XS]
    float* s_inv  = SB + 48 * XS;         // [512]

    int blk = blockIdx.x;                  // 0..1023
    int bb = blk >> 3, chunk = blk & 7;
    int t = threadIdx.x;
    int b = bb >> 5, e = (bb >> 2) & 7, f1 = (bb >> 1) & 1, f2 = bb & 1;
    int g = bb & 15;        // reference's tile() quirk: geo block = bb % 16
    float alpha = salpha[0], beta = sbeta[0];

    const float* xb = x + (((size_t)(b * 256 + e * 32)) << 14) + (f1 * 64) * 128 + f2 * 64;

    // ---- load phase: whole 32x512 x slab, front-batched LDGs, one sync ----
    #pragma unroll
    for (int r = 0; r < 16; r++) {
        int idx = r * 256 + t;             // 4096 float4
        int c = idx >> 7, rest = idx & 127;
        int ir = rest >> 4, j4 = rest & 15;
        *(float4*)&s_x[c * XS + ir * 64 + j4 * 4] =
            *(const float4*)(xb + c * 16384 + (chunk * 8 + ir) * 128 + j4 * 4);
    }
    __syncthreads();

    // ---- norm phase: 512 columns / 256 threads (2 each), conflict-free scalar walk ----
    {
        float ss0 = 0.f, ss1 = 0.f;
        #pragma unroll 8
        for (int c = 0; c < 32; c++) {
            float v0 = s_x[c * XS + t];
            float v1 = s_x[c * XS + t + 256];
            ss0 += v0 * v0; ss1 += v1 * v1;
        }
        s_inv[t]       = 1.f / fmaxf(sqrtf(ss0), 1e-12f);
        s_inv[t + 256] = 1.f / fmaxf(sqrtf(ss1), 1e-12f);
    }
    __syncthreads();

    // ---- phase A: sim rows; map (m = t&15, q = t>>4) so x-LDS has 2 distinct addrs/warp ----
    {
        int m = t & 15, q = t >> 4, j0 = q * 4;
        float4 ncen_r[8];
        #pragma unroll
        for (int c4 = 0; c4 < 8; c4++)
            ncen_r[c4] = *(const float4*)(d_ncen + bb * 512 + m * 32 + c4 * 4);
        const float* sgb = d_sgeo2 + (g * 16 + m) * 4096 + chunk * 512;
        #pragma unroll
        for (int ir = 0; ir < 8; ir++) {
            float4 sg2 = *(const float4*)(sgb + ir * 64 + j0);
            float d0 = 0.f, d1 = 0.f, d2 = 0.f, d3 = 0.f;
            #pragma unroll
            for (int c4 = 0; c4 < 8; c4++) {
                float4 nc = ncen_r[c4];
                float4 xa = *(const float4*)&s_x[(c4 * 4 + 0) * XS + ir * 64 + j0];
                float4 xb_ = *(const float4*)&s_x[(c4 * 4 + 1) * XS + ir * 64 + j0];
                float4 xc = *(const float4*)&s_x[(c4 * 4 + 2) * XS + ir * 64 + j0];
                float4 xd = *(const float4*)&s_x[(c4 * 4 + 3) * XS + ir * 64 + j0];
                d0 += nc.x * xa.x + nc.y * xb_.x + nc.z * xc.x + nc.w * xd.x;
                d1 += nc.x * xa.y + nc.y * xb_.y + nc.z * xc.y + nc.w * xd.y;
                d2 += nc.x * xa.z + nc.y * xb_.z + nc.z * xc.z + nc.w * xd.z;
                d3 += nc.x * xa.w + nc.y * xb_.w + nc.z * xc.w + nc.w * xd.w;
            }
            float4 iv = *(const float4*)&s_inv[ir * 64 + j0];
            float s0 = f2tf(sigmoidf(beta + alpha * d0 * iv.x) * sg2.x);
            float s1 = f2tf(sigmoidf(beta + alpha * d1 * iv.y) * sg2.y);
            float s2 = f2tf(sigmoidf(beta + alpha * d2 * iv.z) * sg2.z);
            float s3 = f2tf(sigmoidf(beta + alpha * d3 * iv.w) * sg2.w);
            *(float4*)&s_sim[m * XS + ir * 64 + j0] = make_float4(s0, s1, s2, s3);
        }
    }
    __syncthreads();

    // ---- coalesced sim -> gmem copy ----
    {
        float* simg = d_sim + (size_t)bb * 65536 + chunk * 512;
        #pragma unroll
        for (int r = 0; r < 8; r++) {
            int idx = r * 256 + t;         // 2048 float4
            int mm = idx >> 7, kk = idx & 127;
            *(float4*)(simg + mm * 4096 + kk * 4) = *(const float4*)&s_sim[mm * XS + kk * 4];
        }
    }

    // ---- phase B: warp-tiled T/S/G; warp w: T-cols w*4+2h+{0,1}, G-row w*2+h, m=lane&15 ----
    {
        int w = t >> 5, l = t & 31;
        int m = l & 15, h = l >> 4;
        int ca = w * 4 + 2 * h;            // T columns ca, ca+1
        int ma = w * 2 + h;                // G row
        float T0 = 0.f, T1 = 0.f, Greg = 0.f, Sacc = 0.f;
        #pragma unroll 4
        for (int k4 = 0; k4 < 128; k4++) {
            float4 a  = *(const float4*)&s_sim[m * XS + k4 * 4];
            float4 xa = *(const float4*)&s_x[ca * XS + k4 * 4];
            float4 xc = *(const float4*)&s_x[(ca + 1) * XS + k4 * 4];
            float4 bq = *(const float4*)&s_sim[ma * XS + k4 * 4];
            T0 += a.x * xa.x + a.y * xa.y + a.z * xa.z + a.w * xa.w;
            T1 += a.x * xc.x + a.y * xc.y + a.z * xc.z + a.w * xc.w;
            Greg += a.x * bq.x + a.y * bq.y + a.z * bq.z + a.w * bq.w;
            if (w == 0 && h == 0) Sacc += (a.x + a.y) + (a.z + a.w);
        }
        d_Tp[blk * 512 + m * 32 + ca]     = T0;
        d_Tp[blk * 512 + m * 32 + ca + 1] = T1;
        d_Gp[blk * 256 + ma * 16 + m] = Greg;  // layout [ma][mb], matches k_dout
        if (w == 0 && h == 0) d_Sp[blk * 16 + m] = Sacc;
    }
}

// ---------- kernel B2: reduce partials -> dout, D, GN stat contributions ----------
__global__ __launch_bounds__(256) void k_dout() {
    __shared__ float s_S[16];
    __shared__ float s_dout[512];
    __shared__ double s_redd[16];
    int bb = blockIdx.x;
    int t = threadIdx.x;
    int b = bb >> 5;

    if (t < 16) {
        float s = 0.f;
        #pragma unroll
        for (int ch = 0; ch < 8; ch++) s += d_Sp[(bb * 8 + ch) * 16 + t];
        s_S[t] = s;
    }
    float Ta = 0.f, Tb = 0.f;
    #pragma unroll
    for (int ch = 0; ch < 8; ch++) {
        Ta += d_Tp[(bb * 8 + ch) * 512 + t];
        Tb += d_Tp[(bb * 8 + ch) * 512 + t + 256];
    }
    float Gf = 0.f;
    #pragma unroll
    for (int ch = 0; ch < 8; ch++) Gf += d_Gp[(bb * 8 + ch) * 256 + t];
    __syncthreads();

    int m1 = t >> 5, m2 = m1 + 8;
    float da = (Ta + d_cen[bb * 512 + t])       / (s_S[m1] + 1.f);
    float db = (Tb + d_cen[bb * 512 + t + 256]) / (s_S[m2] + 1.f);
    s_dout[t] = da; s_dout[t + 256] = db;
    d_dout[bb * 512 + t] = da;
    d_dout[bb * 512 + t + 256] = db;
    __syncthreads();

    int ma = t >> 4, mb = t & 15;
    float D = 0.f;
    #pragma unroll
    for (int c = 0; c < 32; c++) D += s_dout[ma * 32 + c] * s_dout[mb * 32 + c];

    double ds = (double)(da * s_S[m1] + db * s_S[m2]);  // sum(pre) contribution
    double d2 = (double)(Gf * D);                        // sumsq(pre) contribution
    #pragma unroll
    for (int o = 16; o; o >>= 1) {
        ds += __shfl_down_sync(0xffffffffu, ds, o);
        d2 += __shfl_down_sync(0xffffffffu, d2, o);
    }
    int wid = t >> 5, lane = t & 31;
    if (lane == 0) { s_redd[wid] = ds; s_redd[8 + wid] = d2; }
    __syncthreads();
    if (t == 0) {
        double a = 0.0, bq = 0.0;
        for (int w2 = 0; w2 < 8; w2++) { a += s_redd[w2]; bq += s_redd[8 + w2]; }
        atomicAdd(&d_gstats[b * 2], a);
        atomicAdd(&d_gstats[b * 2 + 1], bq);
    }
}

// ---------------- kernel E: fold GN shift into projection bias ----------------
__global__ void k_beff(const float* __restrict__ Wp, const float* __restrict__ gnw,
                       const float* __restrict__ gnb, const float* __restrict__ bp) {
    int q = blockIdx.x * 8 + (threadIdx.x >> 5);   // 1024 warps
    int lane = threadIdx.x & 31;
    int b = q >> 8, o = q & 255;
    double cnt = 4194304.0;
    double mud = d_gstats[b * 2] / cnt;
    double var = d_gstats[b * 2 + 1] / cnt - mud * mud;
    float inv = (float)(1.0 / sqrt(var + 1e-5));
    float mu = (float)mud;
    float acc = 0.f;
    for (int c = lane; c < 256; c += 32) {
        float dc = gnb[c] - mu * inv * gnw[c];
        acc += dc * Wp[o * 256 + c];
    }
    #pragma unroll
    for (int off = 16; off; off >>= 1) acc += __shfl_down_sync(0xffffffffu, acc, off);
    if (lane == 0) d_beff[q] = bp[o] + acc;
}

// -------- kernel WD: WD[tile][o][e*16+m] = inv_b * sum_c Wp[o][e*32+c]*gnw[e*32+c]*dout[bb][m][c] --------
__global__ __launch_bounds__(256) void k_wd(const float* __restrict__ Wp,
                                            const float* __restrict__ gnw) {
    __shared__ float s_dout[512];          // dout * gnw (per-channel)
    int bb = blockIdx.x;
    int t = threadIdx.x;
    int b = bb >> 5, e = (bb >> 2) & 7;
    int tile = b * 4 + (bb & 3);            // (b, f1, f2)
    {
        int c0 = t & 31;
        float gw = gnw[e * 32 + c0];
        s_dout[t]       = d_dout[bb * 512 + t] * gw;
        s_dout[t + 256] = d_dout[bb * 512 + t + 256] * gw;
    }
    double cnt = 4194304.0;
    double mu = d_gstats[b * 2] / cnt;
    double var = d_gstats[b * 2 + 1] / cnt - mu * mu;
    float inv = (float)(1.0 / sqrt(var + 1e-5));
    __syncthreads();
    const float* W = Wp + t * 256 + e * 32;   // row o=t
    float acc[16];
    #pragma unroll
    for (int m = 0; m < 16; m++) acc[m] = 0.f;
    #pragma unroll
    for (int c = 0; c < 32; c++) {
        float wv = W[c];
        #pragma unroll
        for (int m = 0; m < 16; m++) acc[m] += wv * s_dout[m * 32 + c];
    }
    float* dst = d_WD + tile * 32768 + t * 128 + e * 16;
    #pragma unroll
    for (int m = 0; m < 16; m++) dst[m] = f2tf(acc[m] * inv);
}

// -------- kernel F: out[o][n] = silu(beff[o] + WD @ sim), tf32 m16n8k8 --------
// CTA 128o x 128n, 8 warps of 64o x 32n, K=128 in chunks of 32.
__global__ __launch_bounds__(256) void k_out(float* __restrict__ out) {
    __shared__ float SB[8960];              // Ws[128][36] | Ps[32][136]; epilogue Sout[64][132]
    float* Ws = SB;
    float* Ps = SB + 4608;
    int nb = blockIdx.x * 128;              // 32
    int ob = blockIdx.y * 128;              // 2
    int tile = blockIdx.z;                  // 16
    int b = tile >> 2, f1 = (tile >> 1) & 1, f2 = tile & 1;
    int t = threadIdx.x;
    int w = t >> 5, lane = t & 31;
    int g = lane >> 2, tid = lane & 3;
    int wo = w >> 2, wn = w & 3;            // warp: o = wo*64.., n = wn*32..
    const float* W = d_WD + tile * 32768;

    float acc[4][4][4];
    #pragma unroll
    for (int mt = 0; mt < 4; mt++)
        #pragma unroll
        for (int nt = 0; nt < 4; nt++)
            #pragma unroll
            for (int r = 0; r < 4; r++) acc[mt][nt][r] = 0.f;

    for (int k0 = 0; k0 < 128; k0 += 32) {
        #pragma unroll
        for (int r = 0; r < 4; r++) {       // Ws: 128o x 32k (already tf32-rounded)
            int idx = r * 256 + t;
            int o = idx >> 3, k4 = idx & 7;
            *(float4*)&Ws[o * 36 + k4 * 4] =
                *(const float4*)(W + (ob + o) * 128 + k0 + k4 * 4);
        }
        #pragma unroll
        for (int r = 0; r < 4; r++) {       // Ps: 32k x 128n
            int idx = r * 256 + t;
            int k = idx >> 5, n4 = idx & 31;
            int q = k0 + k;                 // q = e*16 + m
            int bbq = b * 32 + (q >> 4) * 4 + f1 * 2 + f2;
            const float* srow = d_sim + (size_t)bbq * 65536 + (q & 15) * 4096 + nb;
            *(float4*)&Ps[k * 136 + n4 * 4] = *(const float4*)(srow + n4 * 4);
        }
        __syncthreads();
        #pragma unroll
        for (int kt = 0; kt < 4; kt++) {    // m16n8k8: 4 k-steps of 8
            unsigned a0[4], a1[4], a2[4], a3[4], b0[4], b1[4];
            #pragma unroll
            for (int mt = 0; mt < 4; mt++) {
                int row = wo * 64 + mt * 16;
                a0[mt] = __float_as_uint(Ws[(row + g) * 36 + kt * 8 + tid]);
                a1[mt] = __float_as_uint(Ws[(row + g + 8) * 36 + kt * 8 + tid]);
                a2[mt] = __float_as_uint(Ws[(row + g) * 36 + kt * 8 + tid + 4]);
                a3[mt] = __float_as_uint(Ws[(row + g + 8) * 36 + kt * 8 + tid + 4]);
            }
            #pragma unroll
            for (int nt = 0; nt < 4; nt++) {
                int col = wn * 32 + nt * 8 + g;
                b0[nt] = __float_as_uint(Ps[(kt * 8 + tid) * 136 + col]);
                b1[nt] = __float_as_uint(Ps[(kt * 8 + tid + 4) * 136 + col]);
            }
            #pragma unroll
            for (int mt = 0; mt < 4; mt++)
                #pragma unroll
                for (int nt = 0; nt < 4; nt++)
                    asm volatile(
                        "mma.sync.aligned.m16n8k8.row.col.f32.tf32.tf32.f32 "
                        "{%0,%1,%2,%3}, {%4,%5,%6,%7}, {%8,%9}, {%0,%1,%2,%3};"
                        : "+f"(acc[mt][nt][0]), "+f"(acc[mt][nt][1]),
                          "+f"(acc[mt][nt][2]), "+f"(acc[mt][nt][3])
                        : "r"(a0[mt]), "r"(a1[mt]), "r"(a2[mt]), "r"(a3[mt]),
                          "r"(b0[nt]), "r"(b1[nt]));
        }
        __syncthreads();
    }

    // epilogue: two o-halves via smem for coalesced float4 stores
    float* Sout = SB;                       // [64][132]
    #pragma unroll
    for (int h = 0; h < 2; h++) {
        if (wo == h) {
            #pragma unroll
            for (int mt = 0; mt < 4; mt++) {
                int r0 = mt * 16 + g;
                #pragma unroll
                for (int nt = 0; nt < 4; nt++) {
                    int col = wn * 32 + nt * 8 + 2 * tid;
                    Sout[r0 * 132 + col]           = acc[mt][nt][0];
                    Sout[r0 * 132 + col + 1]       = acc[mt][nt][1];
                    Sout[(r0 + 8) * 132 + col]     = acc[mt][nt][2];
                    Sout[(r0 + 8) * 132 + col + 1] = acc[mt][nt][3];
                }
            }
        }
        __syncthreads();
        #pragma unroll
        for (int r = 0; r < 8; r++) {
            int idx = r * 256 + t;          // 2048 float4
            int row = idx >> 5, n4 = idx & 31;
            int o = ob + h * 64 + row;
            float bias = d_beff[b * 256 + o];
            float4 v = *(const float4*)&Sout[row * 132 + n4 * 4];
            float z0 = v.x + bias, z1 = v.y + bias, z2 = v.z + bias, z3 = v.w + bias;
            float4 rr = make_float4(z0 * sigmoidf(z0), z1 * sigmoidf(z1),
                                    z2 * sigmoidf(z2), z3 * sigmoidf(z3));
            int nloc = nb + n4 * 4;
            int irow = nloc >> 6, jcol = nloc & 63;
            float* orow = out + (((size_t)(b * 256 + o)) << 14)
                              + (f1 * 64 + irow) * 128 + f2 * 64 + jcol;
            *(float4*)orow = rr;
        }
        __syncthreads();
    }
}

// ---------------- launch ----------------
extern "C" void kernel_launch(void* const* d_in, const int* in_sizes, int n_in,
                              void* d_out, int out_size) {
    const float* x     = (const float*)d_in[0];
    const float* xyz   = (const float*)d_in[1];
    // d_in[2]=Wv, d_in[3]=bv : dead code (split path multiplied by zero mask)
    const float* Wproj = (const float*)d_in[4];
    const float* bproj = (const float*)d_in[5];
    const float* gnw   = (const float*)d_in[6];
    const float* gnb   = (const float*)d_in[7];
    const float* sa    = (const float*)d_in[8];
    const float* sb    = (const float*)d_in[9];
    float* out = (float*)d_out;

    cudaFuncSetAttribute(k_simT, cudaFuncAttributeMaxDynamicSharedMemorySize, SMEMT);

    k_centers<<<8192, 256>>>(x);
    k_ncen<<<256, 256>>>();
    k_geo<<<1, 256>>>(xyz);
    k_geo2<<<dim3(16, 64), 256>>>(xyz, sa, sb);
    k_simT<<<1024, 256, SMEMT>>>(x, sa, sb);
    k_dout<<<128, 256>>>();
    k_beff<<<128, 256>>>(Wproj, gnw, gnb, bproj);
    k_wd<<<128, 256>>>(Wproj, gnw);
    k_out<<<dim3(32, 2, 16), 256>>>(out);
}

// round 13
// speedup vs baseline: 1.2738x; 1.0348x over previous
#include <cuda_runtime.h>
#include <math.h>

// x: (4,256,128,128)  xyz: (4,3,128,128)
// folded blocks: NB=128 (b*32 + e*4 + f1*2 + f2), c=32, tile 64x64, M=16 centers
#define NB 128
#define MCNT 16

// ---------------- scratch (static __device__, no allocation) ----------------
__device__ float  d_cen [NB*512];         // pooled centers (unnormalized)
__device__ float  d_ncen[NB*512];         // l2-normalized centers
__device__ float  d_ngeo[16*16*4];        // normalized xyz centers, padded to 4
__device__ float  d_sgeo2[16*16*4096];    // sigmoid(geo)^2 table  [g][m][n]  (4 MB)
__device__ float  d_sim [NB*16*4096];     // 33.5 MB sim cache (tf32-rounded values)
__device__ float  d_Tp  [1024*512];       // partial T = sim@x  (per bb-chunk)
__device__ float  d_Sp  [1024*16];        // partial rowsum(sim)
__device__ float  d_Gp  [1024*256];       // partial Gram(sim)
__device__ float  d_dout[NB*512];         // dense_out (16m x 32c per bb)
__device__ double d_gstats[8];            // per-batch sum, sumsq
__device__ float  d_beff[4*256];          // GN-folded projection bias
__device__ float  d_WD  [16*256*128];     // fused weights (tf32-rounded)

__device__ __forceinline__ float sigmoidf(float z) { return 1.f / (1.f + __expf(-z)); }
__device__ __forceinline__ float f2tf(float f) {
    unsigned u; asm("cvt.rna.tf32.f32 %0, %1;" : "=r"(u) : "f"(f));
    return __uint_as_float(u);
}
__device__ __forceinline__ void cp16(void* dst_smem, const void* src_gmem) {
    unsigned d = (unsigned)__cvta_generic_to_shared(dst_smem);
    asm volatile("cp.async.cg.shared.global [%0], [%1], 16;" :: "r"(d), "l"(src_gmem));
}

// ------- kernel A: pooled centers, warp per (bb,pi,c), full-row coalesced -------
__global__ void k_centers(const float* __restrict__ x) {
    int w = blockIdx.x * 8 + (threadIdx.x >> 5);   // 16384 warps
    int lane = threadIdx.x & 31;
    int bb = w >> 7; int rem = w & 127; int pi = rem >> 5; int c = rem & 31;
    int b = bb >> 5, e = (bb >> 2) & 7, f1 = (bb >> 1) & 1, f2 = bb & 1;
    const float* base = x + (((size_t)(b * 256 + e * 32 + c)) << 14)
                          + (f1 * 64 + pi * 16) * 128 + f2 * 64;
    float acc = 0.f;
    #pragma unroll
    for (int r = 0; r < 8; r++) {
        int linear = r * 32 + lane;            // 256 float4 = 16 rows x 16 float4
        int row = linear >> 4, j4 = linear & 15;
        float4 v = *(const float4*)(base + row * 128 + j4 * 4);
        acc += (v.x + v.y) + (v.z + v.w);
    }
    // pj = (lane&15)>>2 is lane-constant; reduce the 8 lanes sharing each pj
    acc += __shfl_down_sync(0xffffffffu, acc, 16);
    acc += __shfl_down_sync(0xffffffffu, acc, 2);
    acc += __shfl_down_sync(0xffffffffu, acc, 1);
    if (lane < 16 && (lane & 3) == 0) {
        int pj = lane >> 2;
        d_cen[bb * 512 + (pi * 4 + pj) * 32 + c] = acc * (1.f / 256.f);
    }
}

// ---------------- kernel A2: normalize centers, warp per (bb,m) ----------------
__global__ void k_ncen() {
    int q = blockIdx.x * 8 + (threadIdx.x >> 5);   // 2048 warps
    int c = threadIdx.x & 31;
    float v = d_cen[q * 32 + c];
    float ss = v * v;
    #pragma unroll
    for (int o = 16; o; o >>= 1) ss += __shfl_xor_sync(0xffffffffu, ss, o);
    float inv = 1.f / fmaxf(sqrtf(ss), 1e-12f);
    d_ncen[q * 32 + c] = v * inv;
}

// ---------------- kernel A3: normalized xyz centers + zero stats ----------------
__global__ void k_geo(const float* __restrict__ xyz) {
    int t = threadIdx.x;
    if (t < 8) d_gstats[t] = 0.0;
    int g = t >> 4, m = t & 15;
    int b = g >> 2, f1 = (g >> 1) & 1, f2 = g & 1;
    int pi = m >> 2, pj = m & 3;
    const float* base = xyz + (((size_t)(b * 3)) << 14)
                            + (f1 * 64 + pi * 16) * 128 + f2 * 64 + pj * 16;
    float s0 = 0.f, s1 = 0.f, s2 = 0.f;
    for (int ii = 0; ii < 16; ii++)
        for (int jj = 0; jj < 16; jj++) {
            int off = ii * 128 + jj;
            s0 += base[off];
            s1 += base[off + 16384];
            s2 += base[off + 32768];
        }
    s0 *= (1.f / 256.f); s1 *= (1.f / 256.f); s2 *= (1.f / 256.f);
    float inv = 1.f / fmaxf(sqrtf(s0 * s0 + s1 * s1 + s2 * s2), 1e-12f);
    int o = (g * 16 + m) * 4;
    d_ngeo[o] = s0 * inv; d_ngeo[o + 1] = s1 * inv; d_ngeo[o + 2] = s2 * inv; d_ngeo[o + 3] = 0.f;
}

// ---------------- kernel A4: sim_geo^2 table [g][m][n], grid (16 g, 64 i) ----------------
__global__ void k_geo2(const float* __restrict__ xyz,
                       const float* __restrict__ salpha, const float* __restrict__ sbeta) {
    int g = blockIdx.x, i = blockIdx.y;
    int t = threadIdx.x;
    int j = t & 63, mg = t >> 6;                 // 4 m-groups of 4
    int bg = g >> 2, f1 = (g >> 1) & 1, f2 = g & 1;
    float alpha = salpha[0], beta = sbeta[0];
    const float* base = xyz + (((size_t)(bg * 3)) << 14) + (f1 * 64 + i) * 128 + f2 * 64 + j;
    float p0 = base[0], p1 = base[16384], p2 = base[32768];
    float inv = 1.f / fmaxf(sqrtf(p0 * p0 + p1 * p1 + p2 * p2), 1e-12f);
    p0 *= inv; p1 *= inv; p2 *= inv;
    #pragma unroll
    for (int mm = 0; mm < 4; mm++) {
        int m = mg * 4 + mm;
        const float* ng = d_ngeo + (g * 16 + m) * 4;
        float gd = ng[0] * p0 + ng[1] * p1 + ng[2] * p2;
        float sg = sigmoidf(beta + alpha * gd);
        d_sgeo2[(g * 16 + m) * 4096 + i * 64 + j] = sg * sg;
    }
}

// ------- fused kernel: sim (phase A) + T/S/G reduction (phase B), big smem -------
// CTA per (bb, 8-row chunk). 3 syncs. Crossbar-optimized lane maps.
#define XS 516
#define SMEMT ((48*XS + 512) * 4)
__global__ __launch_bounds__(256) void k_simT(const float* __restrict__ x,
                                              const float* __restrict__ salpha,
                                              const float* __restrict__ sbeta) {
    extern __shared__ float SB[];
    float* s_x    = SB;                   // [32][XS]
    float* s_sim  = SB + 32 * XS;         // [16][XS]
    float* s_inv  = SB + 48 * XS;         // [512]

    int blk = blockIdx.x;                  // 0..1023
    int bb = blk >> 3, chunk = blk & 7;
    int t = threadIdx.x;
    int b = bb >> 5, e = (bb >> 2) & 7, f1 = (bb >> 1) & 1, f2 = bb & 1;
    int g = bb & 15;        // reference's tile() quirk: geo block = bb % 16
    float alpha = salpha[0], beta = sbeta[0];

    const float* xb = x + (((size_t)(b * 256 + e * 32)) << 14) + (f1 * 64) * 128 + f2 * 64;

    // ---- load phase: whole 32x512 x slab, front-batched LDGs, one sync ----
    #pragma unroll
    for (int r = 0; r < 16; r++) {
        int idx = r * 256 + t;             // 4096 float4
        int c = idx >> 7, rest = idx & 127;
        int ir = rest >> 4, j4 = rest & 15;
        *(float4*)&s_x[c * XS + ir * 64 + j4 * 4] =
            *(const float4*)(xb + c * 16384 + (chunk * 8 + ir) * 128 + j4 * 4);
    }
    __syncthreads();

    // ---- norm phase: 512 columns / 256 threads (2 each), conflict-free scalar walk ----
    {
        float ss0 = 0.f, ss1 = 0.f;
        #pragma unroll 8
        for (int c = 0; c < 32; c++) {
            float v0 = s_x[c * XS + t];
            float v1 = s_x[c * XS + t + 256];
            ss0 += v0 * v0; ss1 += v1 * v1;
        }
        s_inv[t]       = 1.f / fmaxf(sqrtf(ss0), 1e-12f);
        s_inv[t + 256] = 1.f / fmaxf(sqrtf(ss1), 1e-12f);
    }
    __syncthreads();

    // ---- phase A: sim rows; map (m = t&15, q = t>>4) so x-LDS has 2 distinct addrs/warp ----
    {
        int m = t & 15, q = t >> 4, j0 = q * 4;
        float4 ncen_r[8];
        #pragma unroll
        for (int c4 = 0; c4 < 8; c4++)
            ncen_r[c4] = *(const float4*)(d_ncen + bb * 512 + m * 32 + c4 * 4);
        const float* sgb = d_sgeo2 + (g * 16 + m) * 4096 + chunk * 512;
        #pragma unroll
        for (int ir = 0; ir < 8; ir++) {
            float4 sg2 = *(const float4*)(sgb + ir * 64 + j0);
            float d0 = 0.f, d1 = 0.f, d2 = 0.f, d3 = 0.f;
            #pragma unroll
            for (int c4 = 0; c4 < 8; c4++) {
                float4 nc = ncen_r[c4];
                float4 xa = *(const float4*)&s_x[(c4 * 4 + 0) * XS + ir * 64 + j0];
                float4 xb_ = *(const float4*)&s_x[(c4 * 4 + 1) * XS + ir * 64 + j0];
                float4 xc = *(const float4*)&s_x[(c4 * 4 + 2) * XS + ir * 64 + j0];
                float4 xd = *(const float4*)&s_x[(c4 * 4 + 3) * XS + ir * 64 + j0];
                d0 += nc.x * xa.x + nc.y * xb_.x + nc.z * xc.x + nc.w * xd.x;
                d1 += nc.x * xa.y + nc.y * xb_.y + nc.z * xc.y + nc.w * xd.y;
                d2 += nc.x * xa.z + nc.y * xb_.z + nc.z * xc.z + nc.w * xd.z;
                d3 += nc.x * xa.w + nc.y * xb_.w + nc.z * xc.w + nc.w * xd.w;
            }
            float4 iv = *(const float4*)&s_inv[ir * 64 + j0];
            float s0 = f2tf(sigmoidf(beta + alpha * d0 * iv.x) * sg2.x);
            float s1 = f2tf(sigmoidf(beta + alpha * d1 * iv.y) * sg2.y);
            float s2 = f2tf(sigmoidf(beta + alpha * d2 * iv.z) * sg2.z);
            float s3 = f2tf(sigmoidf(beta + alpha * d3 * iv.w) * sg2.w);
            *(float4*)&s_sim[m * XS + ir * 64 + j0] = make_float4(s0, s1, s2, s3);
        }
    }
    __syncthreads();

    // ---- coalesced sim -> gmem copy ----
    {
        float* simg = d_sim + (size_t)bb * 65536 + chunk * 512;
        #pragma unroll
        for (int r = 0; r < 8; r++) {
            int idx = r * 256 + t;         // 2048 float4
            int mm = idx >> 7, kk = idx & 127;
            *(float4*)(simg + mm * 4096 + kk * 4) = *(const float4*)&s_sim[mm * XS + kk * 4];
        }
    }

    // ---- phase B: warp-tiled T/S/G; warp w: T-cols w*4+2h+{0,1}, G-row w*2+h, m=lane&15 ----
    {
        int w = t >> 5, l = t & 31;
        int m = l & 15, h = l >> 4;
        int ca = w * 4 + 2 * h;            // T columns ca, ca+1
        int ma = w * 2 + h;                // G row
        float T0 = 0.f, T1 = 0.f, Greg = 0.f, Sacc = 0.f;
        #pragma unroll 4
        for (int k4 = 0; k4 < 128; k4++) {
            float4 a  = *(const float4*)&s_sim[m * XS + k4 * 4];
            float4 xa = *(const float4*)&s_x[ca * XS + k4 * 4];
            float4 xc = *(const float4*)&s_x[(ca + 1) * XS + k4 * 4];
            float4 bq = *(const float4*)&s_sim[ma * XS + k4 * 4];
            T0 += a.x * xa.x + a.y * xa.y + a.z * xa.z + a.w * xa.w;
            T1 += a.x * xc.x + a.y * xc.y + a.z * xc.z + a.w * xc.w;
            Greg += a.x * bq.x + a.y * bq.y + a.z * bq.z + a.w * bq.w;
            if (w == 0 && h == 0) Sacc += (a.x + a.y) + (a.z + a.w);
        }
        d_Tp[blk * 512 + m * 32 + ca]     = T0;
        d_Tp[blk * 512 + m * 32 + ca + 1] = T1;
        d_Gp[blk * 256 + ma * 16 + m] = Greg;  // layout [ma][mb], matches k_dout
        if (w == 0 && h == 0) d_Sp[blk * 16 + m] = Sacc;
    }
}

// ---------- kernel B2: reduce partials -> dout, D, GN stat contributions ----------
__global__ __launch_bounds__(256) void k_dout() {
    __shared__ float s_S[16];
    __shared__ float s_dout[512];
    __shared__ double s_redd[16];
    int bb = blockIdx.x;
    int t = threadIdx.x;
    int b = bb >> 5;

    if (t < 16) {
        float s = 0.f;
        #pragma unroll
        for (int ch = 0; ch < 8; ch++) s += d_Sp[(bb * 8 + ch) * 16 + t];
        s_S[t] = s;
    }
    float Ta = 0.f, Tb = 0.f;
    #pragma unroll
    for (int ch = 0; ch < 8; ch++) {
        Ta += d_Tp[(bb * 8 + ch) * 512 + t];
        Tb += d_Tp[(bb * 8 + ch) * 512 + t + 256];
    }
    float Gf = 0.f;
    #pragma unroll
    for (int ch = 0; ch < 8; ch++) Gf += d_Gp[(bb * 8 + ch) * 256 + t];
    __syncthreads();

    int m1 = t >> 5, m2 = m1 + 8;
    float da = (Ta + d_cen[bb * 512 + t])       / (s_S[m1] + 1.f);
    float db = (Tb + d_cen[bb * 512 + t + 256]) / (s_S[m2] + 1.f);
    s_dout[t] = da; s_dout[t + 256] = db;
    d_dout[bb * 512 + t] = da;
    d_dout[bb * 512 + t + 256] = db;
    __syncthreads();

    int ma = t >> 4, mb = t & 15;
    float D = 0.f;
    #pragma unroll
    for (int c = 0; c < 32; c++) D += s_dout[ma * 32 + c] * s_dout[mb * 32 + c];

    double ds = (double)(da * s_S[m1] + db * s_S[m2]);  // sum(pre) contribution
    double d2 = (double)(Gf * D);                        // sumsq(pre) contribution
    #pragma unroll
    for (int o = 16; o; o >>= 1) {
        ds += __shfl_down_sync(0xffffffffu, ds, o);
        d2 += __shfl_down_sync(0xffffffffu, d2, o);
    }
    int wid = t >> 5, lane = t & 31;
    if (lane == 0) { s_redd[wid] = ds; s_redd[8 + wid] = d2; }
    __syncthreads();
    if (t == 0) {
        double a = 0.0, bq = 0.0;
        for (int w2 = 0; w2 < 8; w2++) { a += s_redd[w2]; bq += s_redd[8 + w2]; }
        atomicAdd(&d_gstats[b * 2], a);
        atomicAdd(&d_gstats[b * 2 + 1], bq);
    }
}

// ---------------- kernel E: fold GN shift into projection bias ----------------
__global__ void k_beff(const float* __restrict__ Wp, const float* __restrict__ gnw,
                       const float* __restrict__ gnb, const float* __restrict__ bp) {
    int q = blockIdx.x * 8 + (threadIdx.x >> 5);   // 1024 warps
    int lane = threadIdx.x & 31;
    int b = q >> 8, o = q & 255;
    double cnt = 4194304.0;
    double mud = d_gstats[b * 2] / cnt;
    double var = d_gstats[b * 2 + 1] / cnt - mud * mud;
    float inv = (float)(1.0 / sqrt(var + 1e-5));
    float mu = (float)mud;
    float acc = 0.f;
    for (int c = lane; c < 256; c += 32) {
        float dc = gnb[c] - mu * inv * gnw[c];
        acc += dc * Wp[o * 256 + c];
    }
    #pragma unroll
    for (int off = 16; off; off >>= 1) acc += __shfl_down_sync(0xffffffffu, acc, off);
    if (lane == 0) d_beff[q] = bp[o] + acc;
}

// -------- kernel WD: WD[tile][o][e*16+m] = inv_b * sum_c Wp[o][e*32+c]*gnw[e*32+c]*dout[bb][m][c] --------
__global__ __launch_bounds__(256) void k_wd(const float* __restrict__ Wp,
                                            const float* __restrict__ gnw) {
    __shared__ float s_dout[512];          // dout * gnw (per-channel)
    int bb = blockIdx.x;
    int t = threadIdx.x;
    int b = bb >> 5, e = (bb >> 2) & 7;
    int tile = b * 4 + (bb & 3);            // (b, f1, f2)
    {
        int c0 = t & 31;
        float gw = gnw[e * 32 + c0];
        s_dout[t]       = d_dout[bb * 512 + t] * gw;
        s_dout[t + 256] = d_dout[bb * 512 + t + 256] * gw;
    }
    double cnt = 4194304.0;
    double mu = d_gstats[b * 2] / cnt;
    double var = d_gstats[b * 2 + 1] / cnt - mu * mu;
    float inv = (float)(1.0 / sqrt(var + 1e-5));
    __syncthreads();
    const float* W = Wp + t * 256 + e * 32;   // row o=t
    float acc[16];
    #pragma unroll
    for (int m = 0; m < 16; m++) acc[m] = 0.f;
    #pragma unroll
    for (int c = 0; c < 32; c++) {
        float wv = W[c];
        #pragma unroll
        for (int m = 0; m < 16; m++) acc[m] += wv * s_dout[m * 32 + c];
    }
    float* dst = d_WD + tile * 32768 + t * 128 + e * 16;
    #pragma unroll
    for (int m = 0; m < 16; m++) dst[m] = f2tf(acc[m] * inv);
}

// -------- kernel F: out = silu(beff + WD @ sim), tf32 m16n8k8, cp.async 2-stage --------
// CTA 128o x 128n, 8 warps of 64o x 32n, K=128 in chunks of 32.
#define STG 8960                            // floats per stage: Ws[128][36] + Ps[32][136]
#define SMEMO (2 * STG * 4)
__global__ __launch_bounds__(256) void k_out(float* __restrict__ out) {
    extern __shared__ float SB[];           // 2 stages; epilogue Sout aliases stage 0
    int nb = blockIdx.x * 128;              // 32
    int ob = blockIdx.y * 128;              // 2
    int tile = blockIdx.z;                  // 16
    int b = tile >> 2, f1 = (tile >> 1) & 1, f2 = tile & 1;
    int t = threadIdx.x;
    int w = t >> 5, lane = t & 31;
    int g = lane >> 2, tid = lane & 3;
    int wo = w >> 2, wn = w & 3;            // warp: o = wo*64.., n = wn*32..
    const float* W = d_WD + tile * 32768;

    // per-thread source/dest indices for the fill (invariant across chunks)
    int woA = (0 * 256 + t) >> 3, wkA = (0 * 256 + t) & 7;   // r expanded below
    (void)woA; (void)wkA;

    float acc[4][4][4];
    #pragma unroll
    for (int mt = 0; mt < 4; mt++)
        #pragma unroll
        for (int nt = 0; nt < 4; nt++)
            #pragma unroll
            for (int r = 0; r < 4; r++) acc[mt][nt][r] = 0.f;

    // issue one chunk's loads into a stage
    auto issue = [&](int stage, int k0) {
        float* Ws = SB + stage * STG;
        float* Ps = Ws + 4608;
        #pragma unroll
        for (int r = 0; r < 4; r++) {       // Ws: 128o x 32k
            int idx = r * 256 + t;
            int o = idx >> 3, k4 = idx & 7;
            cp16(&Ws[o * 36 + k4 * 4], W + (ob + o) * 128 + k0 + k4 * 4);
        }
        #pragma unroll
        for (int r = 0; r < 4; r++) {       // Ps: 32k x 128n
            int idx = r * 256 + t;
            int k = idx >> 5, n4 = idx & 31;
            int q = k0 + k;                 // q = e*16 + m
            int bbq = b * 32 + (q >> 4) * 4 + f1 * 2 + f2;
            const float* srow = d_sim + (size_t)bbq * 65536 + (q & 15) * 4096 + nb;
            cp16(&Ps[k * 136 + n4 * 4], srow + n4 * 4);
        }
        asm volatile("cp.async.commit_group;");
    };

    issue(0, 0);
    for (int ki = 0; ki < 4; ki++) {
        if (ki < 3) {
            issue((ki + 1) & 1, (ki + 1) * 32);
            asm volatile("cp.async.wait_group 1;");
        } else {
            asm volatile("cp.async.wait_group 0;");
        }
        __syncthreads();
        float* Ws = SB + (ki & 1) * STG;
        float* Ps = Ws + 4608;
        #pragma unroll
        for (int kt = 0; kt < 4; kt++) {    // m16n8k8: 4 k-steps of 8
            unsigned a0[4], a1[4], a2[4], a3[4], b0[4], b1[4];
            #pragma unroll
            for (int mt = 0; mt < 4; mt++) {
                int row = wo * 64 + mt * 16;
                a0[mt] = __float_as_uint(Ws[(row + g) * 36 + kt * 8 + tid]);
                a1[mt] = __float_as_uint(Ws[(row + g + 8) * 36 + kt * 8 + tid]);
                a2[mt] = __float_as_uint(Ws[(row + g) * 36 + kt * 8 + tid + 4]);
                a3[mt] = __float_as_uint(Ws[(row + g + 8) * 36 + kt * 8 + tid + 4]);
            }
            #pragma unroll
            for (int nt = 0; nt < 4; nt++) {
                int col = wn * 32 + nt * 8 + g;
                b0[nt] = __float_as_uint(Ps[(kt * 8 + tid) * 136 + col]);
                b1[nt] = __float_as_uint(Ps[(kt * 8 + tid + 4) * 136 + col]);
            }
            #pragma unroll
            for (int mt = 0; mt < 4; mt++)
                #pragma unroll
                for (int nt = 0; nt < 4; nt++)
                    asm volatile(
                        "mma.sync.aligned.m16n8k8.row.col.f32.tf32.tf32.f32 "
                        "{%0,%1,%2,%3}, {%4,%5,%6,%7}, {%8,%9}, {%0,%1,%2,%3};"
                        : "+f"(acc[mt][nt][0]), "+f"(acc[mt][nt][1]),
                          "+f"(acc[mt][nt][2]), "+f"(acc[mt][nt][3])
                        : "r"(a0[mt]), "r"(a1[mt]), "r"(a2[mt]), "r"(a3[mt]),
                          "r"(b0[nt]), "r"(b1[nt]));
        }
        __syncthreads();
    }

    // epilogue: two o-halves via smem (stage 0) for coalesced float4 stores
    float* Sout = SB;                       // [64][132] = 8448 <= STG
    #pragma unroll
    for (int h = 0; h < 2; h++) {
        if (wo == h) {
            #pragma unroll
            for (int mt = 0; mt < 4; mt++) {
                int r0 = mt * 16 + g;
                #pragma unroll
                for (int nt = 0; nt < 4; nt++) {
                    int col = wn * 32 + nt * 8 + 2 * tid;
                    Sout[r0 * 132 + col]           = acc[mt][nt][0];
                    Sout[r0 * 132 + col + 1]       = acc[mt][nt][1];
                    Sout[(r0 + 8) * 132 + col]     = acc[mt][nt][2];
                    Sout[(r0 + 8) * 132 + col + 1] = acc[mt][nt][3];
                }
            }
        }
        __syncthreads();
        #pragma unroll
        for (int r = 0; r < 8; r++) {
            int idx = r * 256 + t;          // 2048 float4
            int row = idx >> 5, n4 = idx & 31;
            int o = ob + h * 64 + row;
            float bias = d_beff[b * 256 + o];
            float4 v = *(const float4*)&Sout[row * 132 + n4 * 4];
            float z0 = v.x + bias, z1 = v.y + bias, z2 = v.z + bias, z3 = v.w + bias;
            float4 rr = make_float4(z0 * sigmoidf(z0), z1 * sigmoidf(z1),
                                    z2 * sigmoidf(z2), z3 * sigmoidf(z3));
            int nloc = nb + n4 * 4;
            int irow = nloc >> 6, jcol = nloc & 63;
            float* orow = out + (((size_t)(b * 256 + o)) << 14)
                              + (f1 * 64 + irow) * 128 + f2 * 64 + jcol;
            *(float4*)orow = rr;
        }
        __syncthreads();
    }
}

// ---------------- launch ----------------
extern "C" void kernel_launch(void* const* d_in, const int* in_sizes, int n_in,
                              void* d_out, int out_size) {
    const float* x     = (const float*)d_in[0];
    const float* xyz   = (const float*)d_in[1];
    // d_in[2]=Wv, d_in[3]=bv : dead code (split path multiplied by zero mask)
    const float* Wproj = (const float*)d_in[4];
    const float* bproj = (const float*)d_in[5];
    const float* gnw   = (const float*)d_in[6];
    const float* gnb   = (const float*)d_in[7];
    const float* sa    = (const float*)d_in[8];
    const float* sb    = (const float*)d_in[9];
    float* out = (float*)d_out;

    cudaFuncSetAttribute(k_simT, cudaFuncAttributeMaxDynamicSharedMemorySize, SMEMT);
    cudaFuncSetAttribute(k_out, cudaFuncAttributeMaxDynamicSharedMemorySize, SMEMO);

    k_centers<<<2048, 256>>>(x);
    k_ncen<<<256, 256>>>();
    k_geo<<<1, 256>>>(xyz);
    k_geo2<<<dim3(16, 64), 256>>>(xyz, sa, sb);
    k_simT<<<1024, 256, SMEMT>>>(x, sa, sb);
    k_dout<<<128, 256>>>();
    k_beff<<<128, 256>>>(Wproj, gnw, gnb, bproj);
    k_wd<<<128, 256>>>(Wproj, gnw);
    k_out<<<dim3(32, 2, 16), 256, SMEMO>>>(out);
}

// round 16
// speedup vs baseline: 1.5797x; 1.2402x over previous
#include <cuda_runtime.h>
#include <math.h>

// x: (4,256,128,128)  xyz: (4,3,128,128)
// folded blocks: NB=128 (b*32 + e*4 + f1*2 + f2), c=32, tile 64x64, M=16 centers
#define NB 128
#define MCNT 16

// ---------------- scratch (static __device__, no allocation) ----------------
__device__ float  d_cen [NB*512];         // pooled centers (unnormalized)
__device__ float  d_ncen[NB*512];         // l2-normalized centers
__device__ float  d_ngeo[16*16*4];        // normalized xyz centers, padded to 4
__device__ float  d_sim [NB*16*4096];     // 33.5 MB sim cache (tf32-rounded values)
__device__ float  d_Tp  [1024*512];       // partial T = sim@x  (per bb-chunk)
__device__ float  d_Sp  [1024*16];        // partial rowsum(sim)
__device__ float  d_Gp  [1024*256];       // partial Gram(sim)
__device__ float  d_dout[NB*512];         // dense_out (16m x 32c per bb)
__device__ double d_gstats[8];            // per-batch sum, sumsq
__device__ float  d_beff[4*256];          // GN-folded projection bias
__device__ float  d_WD  [16*256*128];     // fused weights (tf32-rounded)

__device__ __forceinline__ float sigmoidf(float z) { return 1.f / (1.f + __expf(-z)); }
__device__ __forceinline__ float f2tf(float f) {
    unsigned u; asm("cvt.rna.tf32.f32 %0, %1;" : "=r"(u) : "f"(f));
    return __uint_as_float(u);
}
__device__ __forceinline__ void cp16(void* dst_smem, const void* src_gmem) {
    unsigned d = (unsigned)__cvta_generic_to_shared(dst_smem);
    asm volatile("cp.async.cg.shared.global [%0], [%1], 16;" :: "r"(d), "l"(src_gmem));
}

// ------- kernel A: pooled centers, warp per (bb,pi,c), full-row coalesced -------
__global__ void k_centers(const float* __restrict__ x) {
    int w = blockIdx.x * 8 + (threadIdx.x >> 5);   // 16384 warps
    int lane = threadIdx.x & 31;
    int bb = w >> 7; int rem = w & 127; int pi = rem >> 5; int c = rem & 31;
    int b = bb >> 5, e = (bb >> 2) & 7, f1 = (bb >> 1) & 1, f2 = bb & 1;
    const float* base = x + (((size_t)(b * 256 + e * 32 + c)) << 14)
                          + (f1 * 64 + pi * 16) * 128 + f2 * 64;
    float acc = 0.f;
    #pragma unroll
    for (int r = 0; r < 8; r++) {
        int linear = r * 32 + lane;            // 256 float4 = 16 rows x 16 float4
        int row = linear >> 4, j4 = linear & 15;
        float4 v = *(const float4*)(base + row * 128 + j4 * 4);
        acc += (v.x + v.y) + (v.z + v.w);
    }
    // pj = (lane&15)>>2 is lane-constant; reduce the 8 lanes sharing each pj
    acc += __shfl_down_sync(0xffffffffu, acc, 16);
    acc += __shfl_down_sync(0xffffffffu, acc, 2);
    acc += __shfl_down_sync(0xffffffffu, acc, 1);
    if (lane < 16 && (lane & 3) == 0) {
        int pj = lane >> 2;
        d_cen[bb * 512 + (pi * 4 + pj) * 32 + c] = acc * (1.f / 256.f);
    }
}

// ---------------- kernel A2: normalize centers, warp per (bb,m) ----------------
__global__ void k_ncen() {
    int q = blockIdx.x * 8 + (threadIdx.x >> 5);   // 2048 warps
    int c = threadIdx.x & 31;
    float v = d_cen[q * 32 + c];
    float ss = v * v;
    #pragma unroll
    for (int o = 16; o; o >>= 1) ss += __shfl_xor_sync(0xffffffffu, ss, o);
    float inv = 1.f / fmaxf(sqrtf(ss), 1e-12f);
    d_ncen[q * 32 + c] = v * inv;
}

// ------- kernel A3: normalized xyz centers (warp per (g,m)) + zero stats -------
__global__ void k_geo(const float* __restrict__ xyz) {
    int w = blockIdx.x * 8 + (threadIdx.x >> 5);   // 256 warps
    int lane = threadIdx.x & 31;
    if (blockIdx.x == 0 && threadIdx.x < 8) d_gstats[threadIdx.x] = 0.0;
    int g = w >> 4, m = w & 15;
    int b = g >> 2, f1 = (g >> 1) & 1, f2 = g & 1;
    int pi = m >> 2, pj = m & 3;
    const float* base = xyz + (((size_t)(b * 3)) << 14)
                            + (f1 * 64 + pi * 16) * 128 + f2 * 64 + pj * 16;
    float s0 = 0.f, s1 = 0.f, s2 = 0.f;
    #pragma unroll
    for (int r = 0; r < 8; r++) {
        int p = r * 32 + lane;                 // 256 pool elements
        int ii = p >> 4, jj = p & 15;
        int off = ii * 128 + jj;
        s0 += base[off];
        s1 += base[off + 16384];
        s2 += base[off + 32768];
    }
    #pragma unroll
    for (int o = 16; o; o >>= 1) {
        s0 += __shfl_down_sync(0xffffffffu, s0, o);
        s1 += __shfl_down_sync(0xffffffffu, s1, o);
        s2 += __shfl_down_sync(0xffffffffu, s2, o);
    }
    if (lane == 0) {
        s0 *= (1.f / 256.f); s1 *= (1.f / 256.f); s2 *= (1.f / 256.f);
        float inv = 1.f / fmaxf(sqrtf(s0 * s0 + s1 * s1 + s2 * s2), 1e-12f);
        int o = (g * 16 + m) * 4;
        d_ngeo[o] = s0 * inv; d_ngeo[o + 1] = s1 * inv;
        d_ngeo[o + 2] = s2 * inv; d_ngeo[o + 3] = 0.f;
    }
}

// ------- fused kernel: sim + geo-sigmoid + T/S/G reduction, big smem -------
// CTA per (bb, 8-row chunk). 3 syncs. Crossbar-optimized lane maps.
#define XS 516
#define GS 520
#define SMEMT ((48*XS + 512 + 3*GS) * 4)
__global__ __launch_bounds__(256) void k_simT(const float* __restrict__ x,
                                              const float* __restrict__ xyz,
                                              const float* __restrict__ salpha,
                                              const float* __restrict__ sbeta) {
    extern __shared__ float SB[];
    float* s_x    = SB;                   // [32][XS]
    float* s_sim  = SB + 32 * XS;         // [16][XS]
    float* s_inv  = SB + 48 * XS;         // [512]
    float* s_g    = SB + 48 * XS + 512;   // [3][GS]

    int blk = blockIdx.x;                  // 0..1023
    int bb = blk >> 3, chunk = blk & 7;
    int t = threadIdx.x;
    int b = bb >> 5, e = (bb >> 2) & 7, f1 = (bb >> 1) & 1, f2 = bb & 1;
    int g = bb & 15;        // reference's tile() quirk: geo block = bb % 16
    int bg = g >> 2;
    float alpha = salpha[0], beta = sbeta[0];

    const float* xb = x + (((size_t)(b * 256 + e * 32)) << 14) + (f1 * 64) * 128 + f2 * 64;
    const float* gb = xyz + (((size_t)(bg * 3)) << 14) + (f1 * 64) * 128 + f2 * 64;

    // ---- load phase: whole 32x512 x slab + 3x512 xyz slice, one sync ----
    #pragma unroll
    for (int r = 0; r < 16; r++) {
        int idx = r * 256 + t;             // 4096 float4
        int c = idx >> 7, rest = idx & 127;
        int ir = rest >> 4, j4 = rest & 15;
        *(float4*)&s_x[c * XS + ir * 64 + j4 * 4] =
            *(const float4*)(xb + c * 16384 + (chunk * 8 + ir) * 128 + j4 * 4);
    }
    if (t < 192) {
        #pragma unroll
        for (int r = 0; r < 2; r++) {
            int idx = r * 192 + t;         // 384 float4 = 3ch x 128
            int ch = idx >> 7, rest = idx & 127;
            int ir = rest >> 4, j4 = rest & 15;
            *(float4*)&s_g[ch * GS + ir * 64 + j4 * 4] =
                *(const float4*)(gb + ch * 16384 + (chunk * 8 + ir) * 128 + j4 * 4);
        }
    }
    __syncthreads();

    // ---- norm phase: x column norms (2/thread) + xyz normalize (2/thread) ----
    {
        float ss0 = 0.f, ss1 = 0.f;
        #pragma unroll 8
        for (int c = 0; c < 32; c++) {
            float v0 = s_x[c * XS + t];
            float v1 = s_x[c * XS + t + 256];
            ss0 += v0 * v0; ss1 += v1 * v1;
        }
        s_inv[t]       = 1.f / fmaxf(sqrtf(ss0), 1e-12f);
        s_inv[t + 256] = 1.f / fmaxf(sqrtf(ss1), 1e-12f);
        #pragma unroll
        for (int r = 0; r < 2; r++) {
            int n = r * 256 + t;
            float g0 = s_g[n], g1 = s_g[GS + n], g2 = s_g[2 * GS + n];
            float gi = 1.f / fmaxf(sqrtf(g0 * g0 + g1 * g1 + g2 * g2), 1e-12f);
            s_g[n] = g0 * gi; s_g[GS + n] = g1 * gi; s_g[2 * GS + n] = g2 * gi;
        }
    }
    __syncthreads();

    // ---- phase A: sim rows; map (m = t&15, q = t>>4) so x-LDS has 2 distinct addrs/warp ----
    {
        int m = t & 15, q = t >> 4, j0 = q * 4;
        float4 ncen_r[8];
        #pragma unroll
        for (int c4 = 0; c4 < 8; c4++)
            ncen_r[c4] = *(const float4*)(d_ncen + bb * 512 + m * 32 + c4 * 4);
        float ng0 = d_ngeo[(g * 16 + m) * 4];
        float ng1 = d_ngeo[(g * 16 + m) * 4 + 1];
        float ng2 = d_ngeo[(g * 16 + m) * 4 + 2];
        #pragma unroll
        for (int ir = 0; ir < 8; ir++) {
            float d0 = 0.f, d1 = 0.f, d2 = 0.f, d3 = 0.f;
            #pragma unroll
            for (int c4 = 0; c4 < 8; c4++) {
                float4 nc = ncen_r[c4];
                float4 xa = *(const float4*)&s_x[(c4 * 4 + 0) * XS + ir * 64 + j0];
                float4 xb_ = *(const float4*)&s_x[(c4 * 4 + 1) * XS + ir * 64 + j0];
                float4 xc = *(const float4*)&s_x[(c4 * 4 + 2) * XS + ir * 64 + j0];
                float4 xd = *(const float4*)&s_x[(c4 * 4 + 3) * XS + ir * 64 + j0];
                d0 += nc.x * xa.x + nc.y * xb_.x + nc.z * xc.x + nc.w * xd.x;
                d1 += nc.x * xa.y + nc.y * xb_.y + nc.z * xc.y + nc.w * xd.y;
                d2 += nc.x * xa.z + nc.y * xb_.z + nc.z * xc.z + nc.w * xd.z;
                d3 += nc.x * xa.w + nc.y * xb_.w + nc.z * xc.w + nc.w * xd.w;
            }
            float4 g0v = *(const float4*)&s_g[ir * 64 + j0];
            float4 g1v = *(const float4*)&s_g[GS + ir * 64 + j0];
            float4 g2v = *(const float4*)&s_g[2 * GS + ir * 64 + j0];
            float sga = sigmoidf(beta + alpha * (ng0 * g0v.x + ng1 * g1v.x + ng2 * g2v.x));
            float sgb = sigmoidf(beta + alpha * (ng0 * g0v.y + ng1 * g1v.y + ng2 * g2v.y));
            float sgc = sigmoidf(beta + alpha * (ng0 * g0v.z + ng1 * g1v.z + ng2 * g2v.z));
            float sgd = sigmoidf(beta + alpha * (ng0 * g0v.w + ng1 * g1v.w + ng2 * g2v.w));
            float4 iv = *(const float4*)&s_inv[ir * 64 + j0];
            float s0 = f2tf(sigmoidf(beta + alpha * d0 * iv.x) * (sga * sga));
            float s1 = f2tf(sigmoidf(beta + alpha * d1 * iv.y) * (sgb * sgb));
            float s2 = f2tf(sigmoidf(beta + alpha * d2 * iv.z) * (sgc * sgc));
            float s3 = f2tf(sigmoidf(beta + alpha * d3 * iv.w) * (sgd * sgd));
            *(float4*)&s_sim[m * XS + ir * 64 + j0] = make_float4(s0, s1, s2, s3);
        }
    }
    __syncthreads();

    // ---- coalesced sim -> gmem copy ----
    {
        float* simg = d_sim + (size_t)bb * 65536 + chunk * 512;
        #pragma unroll
        for (int r = 0; r < 8; r++) {
            int idx = r * 256 + t;         // 2048 float4
            int mm = idx >> 7, kk = idx & 127;
            *(float4*)(simg + mm * 4096 + kk * 4) = *(const float4*)&s_sim[mm * XS + kk * 4];
        }
    }

    // ---- phase B: warp-tiled T/S/G; warp w: T-cols w*4+2h+{0,1}, G-row w*2+h, m=lane&15 ----
    {
        int w = t >> 5, l = t & 31;
        int m = l & 15, h = l >> 4;
        int ca = w * 4 + 2 * h;            // T columns ca, ca+1
        int ma = w * 2 + h;                // G row
        float T0 = 0.f, T1 = 0.f, Greg = 0.f, Sacc = 0.f;
        #pragma unroll 4
        for (int k4 = 0; k4 < 128; k4++) {
            float4 a  = *(const float4*)&s_sim[m * XS + k4 * 4];
            float4 xa = *(const float4*)&s_x[ca * XS + k4 * 4];
            float4 xc = *(const float4*)&s_x[(ca + 1) * XS + k4 * 4];
            float4 bq = *(const float4*)&s_sim[ma * XS + k4 * 4];
            T0 += a.x * xa.x + a.y * xa.y + a.z * xa.z + a.w * xa.w;
            T1 += a.x * xc.x + a.y * xc.y + a.z * xc.z + a.w * xc.w;
            Greg += a.x * bq.x + a.y * bq.y + a.z * bq.z + a.w * bq.w;
            if (w == 0 && h == 0) Sacc += (a.x + a.y) + (a.z + a.w);
        }
        d_Tp[blk * 512 + m * 32 + ca]     = T0;
        d_Tp[blk * 512 + m * 32 + ca + 1] = T1;
        d_Gp[blk * 256 + ma * 16 + m] = Greg;  // layout [ma][mb], matches k_dout
        if (w == 0 && h == 0) d_Sp[blk * 16 + m] = Sacc;
    }
}

// ---------- kernel B2: reduce partials -> dout, D, GN stat contributions ----------
__global__ __launch_bounds__(256) void k_dout() {
    __shared__ float s_S[16];
    __shared__ float s_dout[512];
    __shared__ double s_redd[16];
    int bb = blockIdx.x;
    int t = threadIdx.x;
    int b = bb >> 5;

    if (t < 16) {
        float s = 0.f;
        #pragma unroll
        for (int ch = 0; ch < 8; ch++) s += d_Sp[(bb * 8 + ch) * 16 + t];
        s_S[t] = s;
    }
    float Ta = 0.f, Tb = 0.f;
    #pragma unroll
    for (int ch = 0; ch < 8; ch++) {
        Ta += d_Tp[(bb * 8 + ch) * 512 + t];
        Tb += d_Tp[(bb * 8 + ch) * 512 + t + 256];
    }
    float Gf = 0.f;
    #pragma unroll
    for (int ch = 0; ch < 8; ch++) Gf += d_Gp[(bb * 8 + ch) * 256 + t];
    __syncthreads();

    int m1 = t >> 5, m2 = m1 + 8;
    float da = (Ta + d_cen[bb * 512 + t])       / (s_S[m1] + 1.f);
    float db = (Tb + d_cen[bb * 512 + t + 256]) / (s_S[m2] + 1.f);
    s_dout[t] = da; s_dout[t + 256] = db;
    d_dout[bb * 512 + t] = da;
    d_dout[bb * 512 + t + 256] = db;
    __syncthreads();

    int ma = t >> 4, mb = t & 15;
    float D = 0.f;
    #pragma unroll
    for (int c = 0; c < 32; c++) D += s_dout[ma * 32 + c] * s_dout[mb * 32 + c];

    double ds = (double)(da * s_S[m1] + db * s_S[m2]);  // sum(pre) contribution
    double d2 = (double)(Gf * D);                        // sumsq(pre) contribution
    #pragma unroll
    for (int o = 16; o; o >>= 1) {
        ds += __shfl_down_sync(0xffffffffu, ds, o);
        d2 += __shfl_down_sync(0xffffffffu, d2, o);
    }
    int wid = t >> 5, lane = t & 31;
    if (lane == 0) { s_redd[wid] = ds; s_redd[8 + wid] = d2; }
    __syncthreads();
    if (t == 0) {
        double a = 0.0, bq = 0.0;
        for (int w2 = 0; w2 < 8; w2++) { a += s_redd[w2]; bq += s_redd[8 + w2]; }
        atomicAdd(&d_gstats[b * 2], a);
        atomicAdd(&d_gstats[b * 2 + 1], bq);
    }
}

// ---------------- kernel E: fold GN shift into projection bias ----------------
__global__ void k_beff(const float* __restrict__ Wp, const float* __restrict__ gnw,
                       const float* __restrict__ gnb, const float* __restrict__ bp) {
    int q = blockIdx.x * 8 + (threadIdx.x >> 5);   // 1024 warps
    int lane = threadIdx.x & 31;
    int b = q >> 8, o = q & 255;
    double cnt = 4194304.0;
    double mud = d_gstats[b * 2] / cnt;
    double var = d_gstats[b * 2 + 1] / cnt - mud * mud;
    float inv = (float)(1.0 / sqrt(var + 1e-5));
    float mu = (float)mud;
    float acc = 0.f;
    for (int c = lane; c < 256; c += 32) {
        float dc = gnb[c] - mu * inv * gnw[c];
        acc += dc * Wp[o * 256 + c];
    }
    #pragma unroll
    for (int off = 16; off; off >>= 1) acc += __shfl_down_sync(0xffffffffu, acc, off);
    if (lane == 0) d_beff[q] = bp[o] + acc;
}

// -------- kernel WD: WD[tile][o][e*16+m] = inv_b * sum_c Wp[o][e*32+c]*gnw[e*32+c]*dout[bb][m][c] --------
__global__ __launch_bounds__(256) void k_wd(const float* __restrict__ Wp,
                                            const float* __restrict__ gnw) {
    __shared__ float s_dout[512];          // dout * gnw (per-channel)
    int bb = blockIdx.x;
    int t = threadIdx.x;
    int b = bb >> 5, e = (bb >> 2) & 7;
    int tile = b * 4 + (bb & 3);            // (b, f1, f2)
    {
        int c0 = t & 31;
        float gw = gnw[e * 32 + c0];
        s_dout[t]       = d_dout[bb * 512 + t] * gw;
        s_dout[t + 256] = d_dout[bb * 512 + t + 256] * gw;
    }
    double cnt = 4194304.0;
    double mu = d_gstats[b * 2] / cnt;
    double var = d_gstats[b * 2 + 1] / cnt - mu * mu;
    float inv = (float)(1.0 / sqrt(var + 1e-5));
    __syncthreads();
    const float* W = Wp + t * 256 + e * 32;   // row o=t
    float acc[16];
    #pragma unroll
    for (int m = 0; m < 16; m++) acc[m] = 0.f;
    #pragma unroll
    for (int c = 0; c < 32; c++) {
        float wv = W[c];
        #pragma unroll
        for (int m = 0; m < 16; m++) acc[m] += wv * s_dout[m * 32 + c];
    }
    float* dst = d_WD + tile * 32768 + t * 128 + e * 16;
    #pragma unroll
    for (int m = 0; m < 16; m++) dst[m] = f2tf(acc[m] * inv);
}

// -------- kernel F: out = silu(beff + WD @ sim), tf32 m16n8k8, cp.async 2-stage --------
// CTA 128o x 128n, 8 warps of 64o x 32n, K=128 in chunks of 32.
#define STG 8960                            // floats per stage: Ws[128][36] + Ps[32][136]
#define SMEMO (2 * STG * 4)
__global__ __launch_bounds__(256) void k_out(float* __restrict__ out) {
    extern __shared__ float SB[];           // 2 stages; epilogue Sout aliases stage 0
    int nb = blockIdx.x * 128;              // 32
    int ob = blockIdx.y * 128;              // 2
    int tile = blockIdx.z;                  // 16
    int b = tile >> 2, f1 = (tile >> 1) & 1, f2 = tile & 1;
    int t = threadIdx.x;
    int w = t >> 5, lane = t & 31;
    int g = lane >> 2, tid = lane & 3;
    int wo = w >> 2, wn = w & 3;            // warp: o = wo*64.., n = wn*32..
    const float* W = d_WD + tile * 32768;

    float acc[4][4][4];
    #pragma unroll
    for (int mt = 0; mt < 4; mt++)
        #pragma unroll
        for (int nt = 0; nt < 4; nt++)
            #pragma unroll
            for (int r = 0; r < 4; r++) acc[mt][nt][r] = 0.f;

    // issue one chunk's loads into a stage
    auto issue = [&](int stage, int k0) {
        float* Ws = SB + stage * STG;
        float* Ps = Ws + 4608;
        #pragma unroll
        for (int r = 0; r < 4; r++) {       // Ws: 128o x 32k
            int idx = r * 256 + t;
            int o = idx >> 3, k4 = idx & 7;
            cp16(&Ws[o * 36 + k4 * 4], W + (ob + o) * 128 + k0 + k4 * 4);
        }
        #pragma unroll
        for (int r = 0; r < 4; r++) {       // Ps: 32k x 128n
            int idx = r * 256 + t;
            int k = idx >> 5, n4 = idx & 31;
            int q = k0 + k;                 // q = e*16 + m
            int bbq = b * 32 + (q >> 4) * 4 + f1 * 2 + f2;
            const float* srow = d_sim + (size_t)bbq * 65536 + (q & 15) * 4096 + nb;
            cp16(&Ps[k * 136 + n4 * 4], srow + n4 * 4);
        }
        asm volatile("cp.async.commit_group;");
    };

    issue(0, 0);
    for (int ki = 0; ki < 4; ki++) {
        if (ki < 3) {
            issue((ki + 1) & 1, (ki + 1) * 32);
            asm volatile("cp.async.wait_group 1;");
        } else {
            asm volatile("cp.async.wait_group 0;");
        }
        __syncthreads();
        float* Ws = SB + (ki & 1) * STG;
        float* Ps = Ws + 4608;
        #pragma unroll
        for (int kt = 0; kt < 4; kt++) {    // m16n8k8: 4 k-steps of 8
            unsigned a0[4], a1[4], a2[4], a3[4], b0[4], b1[4];
            #pragma unroll
            for (int mt = 0; mt < 4; mt++) {
                int row = wo * 64 + mt * 16;
                a0[mt] = __float_as_uint(Ws[(row + g) * 36 + kt * 8 + tid]);
                a1[mt] = __float_as_uint(Ws[(row + g + 8) * 36 + kt * 8 + tid]);
                a2[mt] = __float_as_uint(Ws[(row + g) * 36 + kt * 8 + tid + 4]);
                a3[mt] = __float_as_uint(Ws[(row + g + 8) * 36 + kt * 8 + tid + 4]);
            }
            #pragma unroll
            for (int nt = 0; nt < 4; nt++) {
                int col = wn * 32 + nt * 8 + g;
                b0[nt] = __float_as_uint(Ps[(kt * 8 + tid) * 136 + col]);
                b1[nt] = __float_as_uint(Ps[(kt * 8 + tid + 4) * 136 + col]);
            }
            #pragma unroll
            for (int mt = 0; mt < 4; mt++)
                #pragma unroll
                for (int nt = 0; nt < 4; nt++)
                    asm volatile(
                        "mma.sync.aligned.m16n8k8.row.col.f32.tf32.tf32.f32 "
                        "{%0,%1,%2,%3}, {%4,%5,%6,%7}, {%8,%9}, {%0,%1,%2,%3};"
                        : "+f"(acc[mt][nt][0]), "+f"(acc[mt][nt][1]),
                          "+f"(acc[mt][nt][2]), "+f"(acc[mt][nt][3])
                        : "r"(a0[mt]), "r"(a1[mt]), "r"(a2[mt]), "r"(a3[mt]),
                          "r"(b0[nt]), "r"(b1[nt]));
        }
        __syncthreads();
    }

    // epilogue: two o-halves via smem (stage 0) for coalesced float4 stores
    float* Sout = SB;                       // [64][132] = 8448 <= STG
    #pragma unroll
    for (int h = 0; h < 2; h++) {
        if (wo == h) {
            #pragma unroll
            for (int mt = 0; mt < 4; mt++) {
                int r0 = mt * 16 + g;
                #pragma unroll
                for (int nt = 0; nt < 4; nt++) {
                    int col = wn * 32 + nt * 8 + 2 * tid;
                    Sout[r0 * 132 + col]           = acc[mt][nt][0];
                    Sout[r0 * 132 + col + 1]       = acc[mt][nt][1];
                    Sout[(r0 + 8) * 132 + col]     = acc[mt][nt][2];
                    Sout[(r0 + 8) * 132 + col + 1] = acc[mt][nt][3];
                }
            }
        }
        __syncthreads();
        #pragma unroll
        for (int r = 0; r < 8; r++) {
            int idx = r * 256 + t;          // 2048 float4
            int row = idx >> 5, n4 = idx & 31;
            int o = ob + h * 64 + row;
            float bias = d_beff[b * 256 + o];
            float4 v = *(const float4*)&Sout[row * 132 + n4 * 4];
            float z0 = v.x + bias, z1 = v.y + bias, z2 = v.z + bias, z3 = v.w + bias;
            float4 rr = make_float4(z0 * sigmoidf(z0), z1 * sigmoidf(z1),
                                    z2 * sigmoidf(z2), z3 * sigmoidf(z3));
            int nloc = nb + n4 * 4;
            int irow = nloc >> 6, jcol = nloc & 63;
            float* orow = out + (((size_t)(b * 256 + o)) << 14)
                              + (f1 * 64 + irow) * 128 + f2 * 64 + jcol;
            *(float4*)orow = rr;
        }
        __syncthreads();
    }
}

// ---------------- launch ----------------
extern "C" void kernel_launch(void* const* d_in, const int* in_sizes, int n_in,
                              void* d_out, int out_size) {
    const float* x     = (const float*)d_in[0];
    const float* xyz   = (const float*)d_in[1];
    // d_in[2]=Wv, d_in[3]=bv : dead code (split path multiplied by zero mask)
    const float* Wproj = (const float*)d_in[4];
    const float* bproj = (const float*)d_in[5];
    const float* gnw   = (const float*)d_in[6];
    const float* gnb   = (const float*)d_in[7];
    const float* sa    = (const float*)d_in[8];
    const float* sb    = (const float*)d_in[9];
    float* out = (float*)d_out;

    cudaFuncSetAttribute(k_simT, cudaFuncAttributeMaxDynamicSharedMemorySize, SMEMT);
    cudaFuncSetAttribute(k_out, cudaFuncAttributeMaxDynamicSharedMemorySize, SMEMO);

    k_centers<<<2048, 256>>>(x);
    k_ncen<<<256, 256>>>();
    k_geo<<<32, 256>>>(xyz);
    k_simT<<<1024, 256, SMEMT>>>(x, xyz, sa, sb);
    k_dout<<<128, 256>>>();
    k_beff<<<128, 256>>>(Wproj, gnw, gnb, bproj);
    k_wd<<<128, 256>>>(Wproj, gnw);
    k_out<<<dim3(32, 2, 16), 256, SMEMO>>>(out);
}